// round 7
// baseline (speedup 1.0000x reference)
#include <cuda_runtime.h>
#include <cuda_bf16.h>
#include <math.h>
#include <stdint.h>

// ===========================================================================
// Problem constants
// ===========================================================================
constexpr int Bb = 4;
constexpr int Ss = 2048;
constexpr int Dd = 1024;
constexpr int MQ = Bb * Ss;                 // 8192

// ===========================================================================
// Scratch (device globals; no allocation allowed)
// ===========================================================================
__device__ __nv_bfloat16 g_xhi[(size_t)MQ * Dd], g_xlo[(size_t)MQ * Dd];
__device__ __nv_bfloat16 g_Wqhi[(size_t)Dd * Dd], g_Wqlo[(size_t)Dd * Dd];
__device__ __nv_bfloat16 g_Wkhi[(size_t)Dd * Dd], g_Wklo[(size_t)Dd * Dd];
__device__ __nv_bfloat16 g_Wvhi[(size_t)Dd * Dd], g_Wvlo[(size_t)Dd * Dd];
__device__ __nv_bfloat16 g_Wohi[(size_t)Dd * Dd], g_Wolo[(size_t)Dd * Dd];
__device__ __nv_bfloat16 g_Qhi[(size_t)MQ * Dd],  g_Qlo[(size_t)MQ * Dd];
__device__ __nv_bfloat16 g_Khi[(size_t)MQ * Dd],  g_Klo[(size_t)MQ * Dd];
__device__ __nv_bfloat16 g_Vthi[(size_t)MQ * Dd], g_Vtlo[(size_t)MQ * Dd];  // [b][d][s]
__device__ float         g_P[(size_t)Bb * Ss * Ss];
__device__ __nv_bfloat16 g_Phi[(size_t)Bb * Ss * Ss], g_Plo[(size_t)Bb * Ss * Ss];
__device__ __nv_bfloat16 g_Ohi[(size_t)MQ * Dd],  g_Olo[(size_t)MQ * Dd];

// ===========================================================================
// Helpers (baseline sm_80+ instructions only; compute_103 has no tcgen05/TMA)
// ===========================================================================
__device__ __forceinline__ uint32_t smem_to_u32(const void* p) {
    uint32_t a;
    asm("{ .reg .u64 t; cvta.to.shared.u64 t, %1; cvt.u32.u64 %0, t; }" : "=r"(a) : "l"(p));
    return a;
}
__device__ __forceinline__ uint32_t swz(uint32_t b) { return b ^ ((b >> 3) & 0x70); }

#define CP_ASYNC16(smem_u32, gptr) \
    asm volatile("cp.async.cg.shared.global [%0], [%1], 16;" :: "r"(smem_u32), "l"(gptr) : "memory")
#define CP_COMMIT() asm volatile("cp.async.commit_group;" ::: "memory")
#define CP_WAIT1()  asm volatile("cp.async.wait_group 1;" ::: "memory")

#define LDSM_X4(r, addr) \
    asm volatile("ldmatrix.sync.aligned.m8n8.x4.shared.b16 {%0,%1,%2,%3}, [%4];" \
        : "=r"((r)[0]), "=r"((r)[1]), "=r"((r)[2]), "=r"((r)[3]) : "r"(addr))

#define MMA16816(d, a, b) \
    asm volatile("mma.sync.aligned.m16n8k16.row.col.f32.bf16.bf16.f32 " \
        "{%0,%1,%2,%3}, {%4,%5,%6,%7}, {%8,%9}, {%0,%1,%2,%3};" \
        : "+f"((d)[0]), "+f"((d)[1]), "+f"((d)[2]), "+f"((d)[3]) \
        : "r"((a)[0]), "r"((a)[1]), "r"((a)[2]), "r"((a)[3]), \
          "r"((b)[0]), "r"((b)[1]))

// ===========================================================================
// Split-bf16 HMMA GEMM:  C = (A @ B^T) * scale (+bias) (*gaussian mask)
// A: [M,K] bf16 hi/lo row-major; B: [N,K] bf16 hi/lo row-major.
// OUT_MODE: 0 = fp32 C; 1 = bf16 hi/lo split C; 2 = bf16 split, V-transposed
// ===========================================================================
constexpr int STAGES = 3;
constexpr int TILE_B = 128 * 128;                  // 16 KB per tile (128 rows x 128B)
constexpr int STAGE_BYTES = 4 * TILE_B;            // Ahi, Alo, Bhi, Blo = 64 KB
constexpr int SMEM_TOTAL = STAGES * STAGE_BYTES + 1024;

template <int OUT_MODE, bool HAS_BIAS, bool MASK>
__global__ __launch_bounds__(256, 1)
void hmma_gemm(const __nv_bfloat16* __restrict__ Ahi, const __nv_bfloat16* __restrict__ Alo,
               const __nv_bfloat16* __restrict__ Bhi, const __nv_bfloat16* __restrict__ Blo,
               const float* __restrict__ bias,
               float* __restrict__ Cf,
               __nv_bfloat16* __restrict__ Chi, __nv_bfloat16* __restrict__ Clo,
               int M, int N, int K, long sA, long sB, long sC, float scale)
{
    extern __shared__ char smem[];
    char* smem_al = (char*)(((uintptr_t)smem + 1023ull) & ~1023ull);
    const uint32_t smem_base = smem_to_u32(smem_al);

    const int tid = threadIdx.x, wid = tid >> 5, lane = tid & 31;
    const int m0 = blockIdx.y * 128, n0 = blockIdx.x * 128;
    const int z = blockIdx.z;
    const int wm = wid >> 2, wn = wid & 3;        // warp tile: 64x32

    Ahi += (long)z * sA;  Alo += (long)z * sA;
    Bhi += (long)z * sB;  Blo += (long)z * sB;

    // --- cp.async geometry: 16KB tile = 1024 chunks of 16B; 4 chunks/thread
    const int r0    = tid >> 3;                   // base row 0..31
    const int colel = (tid & 7) * 8;              // bf16 col within 64-col chunk
    uint32_t so[4];
#pragma unroll
    for (int i = 0; i < 4; i++) so[i] = swz((uint32_t)(r0 + 32 * i) * 128 + (tid & 7) * 16);

    const int nC = K >> 6;

    auto load_chunk = [&](int chunk, int buf) {
        const uint32_t sb = smem_base + buf * STAGE_BYTES;
        const long koff = (long)chunk * 64 + colel;
        const __nv_bfloat16* srcs[4] = {Ahi, Alo, Bhi, Blo};
        const int mn0[4] = {m0, m0, n0, n0};
#pragma unroll
        for (int t = 0; t < 4; t++) {
            const __nv_bfloat16* base = srcs[t] + (long)mn0[t] * K + koff;
            const uint32_t stb = sb + t * TILE_B;
#pragma unroll
            for (int i = 0; i < 4; i++)
                CP_ASYNC16(stb + so[i], base + (long)(r0 + 32 * i) * K);
        }
    };

    // --- ldmatrix lane geometry
    const int arow = (lane & 7) + ((lane >> 3) & 1) * 8;
    const uint32_t acol = ((lane >> 4) & 1) * 16;
    const int brow = (lane & 7) + ((lane >> 4) & 1) * 8;
    const uint32_t bcol = ((lane >> 3) & 1) * 16;
    uint32_t rA[4], rB[2];
#pragma unroll
    for (int mi = 0; mi < 4; mi++) rA[mi] = (uint32_t)(wm * 64 + mi * 16 + arow) * 128;
#pragma unroll
    for (int n2 = 0; n2 < 2; n2++) rB[n2] = (uint32_t)(wn * 32 + n2 * 16 + brow) * 128;

    float acc[4][4][4];
#pragma unroll
    for (int mi = 0; mi < 4; mi++)
#pragma unroll
        for (int ni = 0; ni < 4; ni++)
#pragma unroll
            for (int f = 0; f < 4; f++) acc[mi][ni][f] = 0.f;

    // Pass-reordered compute: writes to the same accumulator are 16 MMAs apart
    auto compute = [&](int buf) {
        const uint32_t sbA = smem_base + buf * STAGE_BYTES;
        const uint32_t sbB = sbA + 2 * TILE_B;
#pragma unroll
        for (int ks = 0; ks < 4; ks++) {
            uint32_t ah[4][4], al[4][4], bh[2][4], bl[2][4];
#pragma unroll
            for (int mi = 0; mi < 4; mi++) {
                LDSM_X4(ah[mi], sbA + swz(rA[mi] + ks * 32 + acol));
                LDSM_X4(al[mi], sbA + TILE_B + swz(rA[mi] + ks * 32 + acol));
            }
#pragma unroll
            for (int n2 = 0; n2 < 2; n2++) {
                LDSM_X4(bh[n2], sbB + swz(rB[n2] + ks * 32 + bcol));
                LDSM_X4(bl[n2], sbB + TILE_B + swz(rB[n2] + ks * 32 + bcol));
            }
            // pass 0: hi*hi
#pragma unroll
            for (int mi = 0; mi < 4; mi++)
#pragma unroll
                for (int ni = 0; ni < 4; ni++)
                    MMA16816(acc[mi][ni], ah[mi], (&bh[ni >> 1][(ni & 1) * 2]));
            // pass 1: hi*lo
#pragma unroll
            for (int mi = 0; mi < 4; mi++)
#pragma unroll
                for (int ni = 0; ni < 4; ni++)
                    MMA16816(acc[mi][ni], ah[mi], (&bl[ni >> 1][(ni & 1) * 2]));
            // pass 2: lo*hi
#pragma unroll
            for (int mi = 0; mi < 4; mi++)
#pragma unroll
                for (int ni = 0; ni < 4; ni++)
                    MMA16816(acc[mi][ni], al[mi], (&bh[ni >> 1][(ni & 1) * 2]));
        }
    };

    // --- pipeline
    load_chunk(0, 0); CP_COMMIT();
    load_chunk(1, 1); CP_COMMIT();

    for (int i = 0; i < nC; i++) {
        CP_WAIT1();
        __syncthreads();
        if (i + 2 < nC) load_chunk(i + 2, (i + 2) % STAGES);
        CP_COMMIT();
        compute(i % STAGES);
    }

    // --- epilogue ----------------------------------------------------------
    constexpr int TP = 136;   // padded row (elements) for the transpose tile
    __nv_bfloat16* Thi = (__nv_bfloat16*)smem_al;
    __nv_bfloat16* Tlo = Thi + 128 * TP;

    if (OUT_MODE == 2) __syncthreads();   // stage buffers are being repurposed

#pragma unroll
    for (int mi = 0; mi < 4; mi++) {
#pragma unroll
        for (int ni = 0; ni < 4; ni++) {
            const float* c = acc[mi][ni];
            const int mA = m0 + wm * 64 + mi * 16 + (lane >> 2);
            const int nA = n0 + wn * 32 + ni * 8 + (lane & 3) * 2;
#pragma unroll
            for (int h = 0; h < 2; h++) {
                const int m = mA + h * 8;
                float v0 = c[2 * h + 0] * scale;
                float v1 = c[2 * h + 1] * scale;
                if (HAS_BIAS) { v0 += bias[nA]; v1 += bias[nA + 1]; }
                if (MASK) {
                    float u0 = ((float)nA       - 0.5f * (float)N) / (0.25f * (float)N);
                    float u1 = ((float)(nA + 1) - 0.5f * (float)N) / (0.25f * (float)N);
                    v0 *= __expf(-0.5f * u0 * u0);
                    v1 *= __expf(-0.5f * u1 * u1);
                }
                if (OUT_MODE == 0) {
                    *(float2*)(Cf + (long)z * sC + (long)m * N + nA) = make_float2(v0, v1);
                } else if (OUT_MODE == 1) {
                    __nv_bfloat16 h0 = __float2bfloat16(v0);
                    __nv_bfloat16 h1 = __float2bfloat16(v1);
                    __nv_bfloat16 l0 = __float2bfloat16(v0 - __bfloat162float(h0));
                    __nv_bfloat16 l1 = __float2bfloat16(v1 - __bfloat162float(h1));
                    const long cb = (long)z * sC + (long)m * N + nA;
                    *(__nv_bfloat162*)(Chi + cb) = __nv_bfloat162(h0, h1);
                    *(__nv_bfloat162*)(Clo + cb) = __nv_bfloat162(l0, l1);
                } else {
                    // stage transposed into smem: T[n_local][m_local]
                    const int ml = m - m0;
                    const int nl0 = nA - n0;
                    __nv_bfloat16 h0 = __float2bfloat16(v0);
                    __nv_bfloat16 h1 = __float2bfloat16(v1);
                    __nv_bfloat16 l0 = __float2bfloat16(v0 - __bfloat162float(h0));
                    __nv_bfloat16 l1 = __float2bfloat16(v1 - __bfloat162float(h1));
                    Thi[nl0 * TP + ml]       = h0;
                    Thi[(nl0 + 1) * TP + ml] = h1;
                    Tlo[nl0 * TP + ml]       = l0;
                    Tlo[(nl0 + 1) * TP + ml] = l1;
                }
            }
        }
    }

    if (OUT_MODE == 2) {
        __syncthreads();
        // coalesced store: Vt[b][n][s]; CTA covers n in [n0,n0+128), s in [s0,s0+128)
        const int r = tid >> 1;               // 0..127 (local n)
        const int half = tid & 1;             // 0/1 -> 64-element halves
        const long gb = ((long)(m0 >> 11) << 21) + ((long)(n0 + r) << 11)
                      + (long)(m0 & 2047) + half * 64;
        const uint4* sh = (const uint4*)(Thi + r * TP + half * 64);
        const uint4* sl = (const uint4*)(Tlo + r * TP + half * 64);
        uint4* dh = (uint4*)(Chi + gb);
        uint4* dl = (uint4*)(Clo + gb);
#pragma unroll
        for (int q = 0; q < 8; q++) dh[q] = sh[q];
#pragma unroll
        for (int q = 0; q < 8; q++) dl[q] = sl[q];
    }
}

// ===========================================================================
// fp32 -> bf16 hi/lo split conversion
// ===========================================================================
__global__ __launch_bounds__(256)
void split_f32(const float* __restrict__ s, __nv_bfloat16* __restrict__ hi,
               __nv_bfloat16* __restrict__ lo, long n4)
{
    long i = (long)blockIdx.x * blockDim.x + threadIdx.x;
    if (i >= n4) return;
    float4 v = *(const float4*)(s + i * 4);
    __nv_bfloat16 h0 = __float2bfloat16(v.x), h1 = __float2bfloat16(v.y);
    __nv_bfloat16 h2 = __float2bfloat16(v.z), h3 = __float2bfloat16(v.w);
    __nv_bfloat16 l0 = __float2bfloat16(v.x - __bfloat162float(h0));
    __nv_bfloat16 l1 = __float2bfloat16(v.y - __bfloat162float(h1));
    __nv_bfloat16 l2 = __float2bfloat16(v.z - __bfloat162float(h2));
    __nv_bfloat16 l3 = __float2bfloat16(v.w - __bfloat162float(h3));
    *(__nv_bfloat162*)(hi + i * 4)     = __nv_bfloat162(h0, h1);
    *(__nv_bfloat162*)(hi + i * 4 + 2) = __nv_bfloat162(h2, h3);
    *(__nv_bfloat162*)(lo + i * 4)     = __nv_bfloat162(l0, l1);
    *(__nv_bfloat162*)(lo + i * 4 + 2) = __nv_bfloat162(l2, l3);
}

// ===========================================================================
// Row softmax (len 2048) fp32 in -> bf16 hi/lo split out
// ===========================================================================
__global__ __launch_bounds__(256)
void softmax_split(const float* __restrict__ P,
                   __nv_bfloat16* __restrict__ Phi, __nv_bfloat16* __restrict__ Plo)
{
    constexpr int VPT = Ss / 256;
    const float* p = P + (long)blockIdx.x * Ss;
    const long ob = (long)blockIdx.x * Ss;
    const int tid = threadIdx.x;

    float vals[VPT];
    float mx = -INFINITY;
#pragma unroll
    for (int i = 0; i < VPT; i++) { vals[i] = p[tid + i * 256]; mx = fmaxf(mx, vals[i]); }

    __shared__ float red[256];
    red[tid] = mx; __syncthreads();
    for (int s = 128; s > 0; s >>= 1) { if (tid < s) red[tid] = fmaxf(red[tid], red[tid + s]); __syncthreads(); }
    mx = red[0]; __syncthreads();

    float sum = 0.f;
#pragma unroll
    for (int i = 0; i < VPT; i++) { vals[i] = __expf(vals[i] - mx); sum += vals[i]; }
    red[tid] = sum; __syncthreads();
    for (int s = 128; s > 0; s >>= 1) { if (tid < s) red[tid] += red[tid + s]; __syncthreads(); }
    const float inv = 1.f / red[0];

#pragma unroll
    for (int i = 0; i < VPT; i++) {
        float v = vals[i] * inv;
        __nv_bfloat16 h = __float2bfloat16(v);
        __nv_bfloat16 l = __float2bfloat16(v - __bfloat162float(h));
        Phi[ob + tid + i * 256] = h;
        Plo[ob + tid + i * 256] = l;
    }
}

// ===========================================================================
extern "C" void kernel_launch(void* const* d_in, const int* in_sizes, int n_in,
                              void* d_out, int out_size)
{
    const float* x  = (const float*)d_in[0];
    const float* Wq = (const float*)d_in[1];
    const float* bq = (const float*)d_in[2];
    const float* Wk = (const float*)d_in[3];
    const float* bk = (const float*)d_in[4];
    const float* Wv = (const float*)d_in[5];
    const float* bv = (const float*)d_in[6];
    const float* Wo = (const float*)d_in[7];
    const float* bo = (const float*)d_in[8];
    float* out = (float*)d_out;

    __nv_bfloat16 *xhi, *xlo, *Wqhi, *Wqlo, *Wkhi, *Wklo, *Wvhi, *Wvlo, *Wohi, *Wolo;
    __nv_bfloat16 *Qhi, *Qlo, *Khi, *Klo, *Vthi, *Vtlo, *Phi, *Plo, *Ohi, *Olo;
    float* P;
    cudaGetSymbolAddress((void**)&xhi, g_xhi);   cudaGetSymbolAddress((void**)&xlo, g_xlo);
    cudaGetSymbolAddress((void**)&Wqhi, g_Wqhi); cudaGetSymbolAddress((void**)&Wqlo, g_Wqlo);
    cudaGetSymbolAddress((void**)&Wkhi, g_Wkhi); cudaGetSymbolAddress((void**)&Wklo, g_Wklo);
    cudaGetSymbolAddress((void**)&Wvhi, g_Wvhi); cudaGetSymbolAddress((void**)&Wvlo, g_Wvlo);
    cudaGetSymbolAddress((void**)&Wohi, g_Wohi); cudaGetSymbolAddress((void**)&Wolo, g_Wolo);
    cudaGetSymbolAddress((void**)&Qhi, g_Qhi);   cudaGetSymbolAddress((void**)&Qlo, g_Qlo);
    cudaGetSymbolAddress((void**)&Khi, g_Khi);   cudaGetSymbolAddress((void**)&Klo, g_Klo);
    cudaGetSymbolAddress((void**)&Vthi, g_Vthi); cudaGetSymbolAddress((void**)&Vtlo, g_Vtlo);
    cudaGetSymbolAddress((void**)&P, g_P);
    cudaGetSymbolAddress((void**)&Phi, g_Phi);   cudaGetSymbolAddress((void**)&Plo, g_Plo);
    cudaGetSymbolAddress((void**)&Ohi, g_Ohi);   cudaGetSymbolAddress((void**)&Olo, g_Olo);

    cudaFuncSetAttribute(hmma_gemm<1, true, false>,  cudaFuncAttributeMaxDynamicSharedMemorySize, SMEM_TOTAL);
    cudaFuncSetAttribute(hmma_gemm<2, true, false>,  cudaFuncAttributeMaxDynamicSharedMemorySize, SMEM_TOTAL);
    cudaFuncSetAttribute(hmma_gemm<0, false, true>,  cudaFuncAttributeMaxDynamicSharedMemorySize, SMEM_TOTAL);
    cudaFuncSetAttribute(hmma_gemm<1, false, false>, cudaFuncAttributeMaxDynamicSharedMemorySize, SMEM_TOTAL);
    cudaFuncSetAttribute(hmma_gemm<0, true, false>,  cudaFuncAttributeMaxDynamicSharedMemorySize, SMEM_TOTAL);

    // 1) split inputs
    split_f32<<<(MQ * Dd / 4 + 255) / 256, 256>>>(x, xhi, xlo, (long)MQ * Dd / 4);
    split_f32<<<(Dd * Dd / 4 + 255) / 256, 256>>>(Wq, Wqhi, Wqlo, (long)Dd * Dd / 4);
    split_f32<<<(Dd * Dd / 4 + 255) / 256, 256>>>(Wk, Wkhi, Wklo, (long)Dd * Dd / 4);
    split_f32<<<(Dd * Dd / 4 + 255) / 256, 256>>>(Wv, Wvhi, Wvlo, (long)Dd * Dd / 4);
    split_f32<<<(Dd * Dd / 4 + 255) / 256, 256>>>(Wo, Wohi, Wolo, (long)Dd * Dd / 4);

    // 2) projections: Q, K (split layout), V (split + transposed to [b][d][s])
    dim3 gproj(Dd / 128, MQ / 128, 1);
    hmma_gemm<1, true, false><<<gproj, 256, SMEM_TOTAL>>>(
        xhi, xlo, Wqhi, Wqlo, bq, nullptr, Qhi, Qlo, MQ, Dd, Dd, 0, 0, 0, 1.f);
    hmma_gemm<1, true, false><<<gproj, 256, SMEM_TOTAL>>>(
        xhi, xlo, Wkhi, Wklo, bk, nullptr, Khi, Klo, MQ, Dd, Dd, 0, 0, 0, 1.f);
    hmma_gemm<2, true, false><<<gproj, 256, SMEM_TOTAL>>>(
        xhi, xlo, Wvhi, Wvlo, bv, nullptr, Vthi, Vtlo, MQ, Dd, Dd, 0, 0, 0, 1.f);

    // 3) scores = (Q @ K^T)/32 * mask(key)  -> fp32 P, batched
    dim3 gsc(Ss / 128, Ss / 128, Bb);
    hmma_gemm<0, false, true><<<gsc, 256, SMEM_TOTAL>>>(
        Qhi, Qlo, Khi, Klo, nullptr, P, nullptr, nullptr,
        Ss, Ss, Dd, (long)Ss * Dd, (long)Ss * Dd, (long)Ss * Ss, 1.f / 32.f);

    // 4) softmax -> P split
    softmax_split<<<Bb * Ss, 256>>>(P, Phi, Plo);

    // 5) O = P @ Vt^T   (Vt rows are head-dims, K-contig over seq)
    dim3 gpv(Dd / 128, Ss / 128, Bb);
    hmma_gemm<1, false, false><<<gpv, 256, SMEM_TOTAL>>>(
        Phi, Plo, Vthi, Vtlo, nullptr, nullptr, Ohi, Olo,
        Ss, Dd, Ss, (long)Ss * Ss, (long)Dd * Ss, (long)Ss * Dd, 1.f);

    // 6) out = O @ Wo^T + bo  -> fp32
    hmma_gemm<0, true, false><<<gproj, 256, SMEM_TOTAL>>>(
        Ohi, Olo, Wohi, Wolo, bo, out, nullptr, nullptr, MQ, Dd, Dd, 0, 0, 0, 1.f);
}

// round 9
// speedup vs baseline: 1.5509x; 1.5509x over previous
#include <cuda_runtime.h>
#include <cuda_bf16.h>
#include <math.h>
#include <stdint.h>

// ===========================================================================
// Problem constants
// ===========================================================================
constexpr int Bb = 4;
constexpr int Ss = 2048;
constexpr int Dd = 1024;
constexpr int MQ = Bb * Ss;                 // 8192

// ===========================================================================
// Scratch (device globals; no allocation allowed)
// ===========================================================================
__device__ __nv_bfloat16 g_xhi[(size_t)MQ * Dd], g_xlo[(size_t)MQ * Dd];
__device__ __nv_bfloat16 g_Wqhi[(size_t)Dd * Dd], g_Wqlo[(size_t)Dd * Dd];
__device__ __nv_bfloat16 g_Wkhi[(size_t)Dd * Dd], g_Wklo[(size_t)Dd * Dd];
__device__ __nv_bfloat16 g_Wvhi[(size_t)Dd * Dd], g_Wvlo[(size_t)Dd * Dd];
__device__ __nv_bfloat16 g_Wohi[(size_t)Dd * Dd], g_Wolo[(size_t)Dd * Dd];
__device__ __nv_bfloat16 g_Qhi[(size_t)MQ * Dd],  g_Qlo[(size_t)MQ * Dd];
__device__ __nv_bfloat16 g_Khi[(size_t)MQ * Dd],  g_Klo[(size_t)MQ * Dd];
__device__ __nv_bfloat16 g_Vthi[(size_t)MQ * Dd], g_Vtlo[(size_t)MQ * Dd];  // [b][d][s]
__device__ float         g_P[(size_t)Bb * Ss * Ss];
__device__ __nv_bfloat16 g_Phi[(size_t)Bb * Ss * Ss], g_Plo[(size_t)Bb * Ss * Ss];
__device__ __nv_bfloat16 g_Ohi[(size_t)MQ * Dd],  g_Olo[(size_t)MQ * Dd];

// ===========================================================================
// Helpers (baseline sm_80+ instructions only; compute_103 has no tcgen05/TMA)
// ===========================================================================
__device__ __forceinline__ uint32_t smem_to_u32(const void* p) {
    uint32_t a;
    asm("{ .reg .u64 t; cvta.to.shared.u64 t, %1; cvt.u32.u64 %0, t; }" : "=r"(a) : "l"(p));
    return a;
}
__device__ __forceinline__ uint32_t swz(uint32_t b) { return b ^ ((b >> 3) & 0x70); }

#define CP_ASYNC16(smem_u32, gptr) \
    asm volatile("cp.async.cg.shared.global [%0], [%1], 16;" :: "r"(smem_u32), "l"(gptr) : "memory")
#define CP_COMMIT() asm volatile("cp.async.commit_group;" ::: "memory")
#define CP_WAIT1()  asm volatile("cp.async.wait_group 1;" ::: "memory")

#define LDSM_X4(r, addr) \
    asm volatile("ldmatrix.sync.aligned.m8n8.x4.shared.b16 {%0,%1,%2,%3}, [%4];" \
        : "=r"((r)[0]), "=r"((r)[1]), "=r"((r)[2]), "=r"((r)[3]) : "r"(addr))

#define MMA16816(d, a, b) \
    asm volatile("mma.sync.aligned.m16n8k16.row.col.f32.bf16.bf16.f32 " \
        "{%0,%1,%2,%3}, {%4,%5,%6,%7}, {%8,%9}, {%0,%1,%2,%3};" \
        : "+f"((d)[0]), "+f"((d)[1]), "+f"((d)[2]), "+f"((d)[3]) \
        : "r"((a)[0]), "r"((a)[1]), "r"((a)[2]), "r"((a)[3]), \
          "r"((b)[0]), "r"((b)[1]))

// ===========================================================================
// Split-bf16 HMMA GEMM:  C = (A @ B^T) * scale (+bias) (*gaussian mask)
// 512 threads, 16 warps in 4x4 grid, warp tile 32x32.
// OUT_MODE: 0 = fp32 C; 1 = bf16 hi/lo split C; 2 = bf16 split, V-transposed
// ===========================================================================
constexpr int STAGES = 3;
constexpr int TILE_B = 128 * 128;                  // 16 KB per tile (128 rows x 128B)
constexpr int STAGE_BYTES = 4 * TILE_B;            // Ahi, Alo, Bhi, Blo = 64 KB
constexpr int SMEM_TOTAL = STAGES * STAGE_BYTES + 1024;

template <int OUT_MODE, bool HAS_BIAS, bool MASK>
__global__ __launch_bounds__(512, 1)
void hmma_gemm(const __nv_bfloat16* __restrict__ Ahi, const __nv_bfloat16* __restrict__ Alo,
               const __nv_bfloat16* __restrict__ Bhi, const __nv_bfloat16* __restrict__ Blo,
               const float* __restrict__ bias,
               float* __restrict__ Cf,
               __nv_bfloat16* __restrict__ Chi, __nv_bfloat16* __restrict__ Clo,
               int M, int N, int K, long sA, long sB, long sC, float scale)
{
    extern __shared__ char smem[];
    char* smem_al = (char*)(((uintptr_t)smem + 1023ull) & ~1023ull);
    const uint32_t smem_base = smem_to_u32(smem_al);

    const int tid = threadIdx.x, wid = tid >> 5, lane = tid & 31;
    const int m0 = blockIdx.y * 128, n0 = blockIdx.x * 128;
    const int z = blockIdx.z;
    const int wm = wid >> 2, wn = wid & 3;        // warp tile: 32x32

    Ahi += (long)z * sA;  Alo += (long)z * sA;
    Bhi += (long)z * sB;  Blo += (long)z * sB;

    // --- cp.async geometry: 16KB tile = 1024 x 16B chunks; 2 chunks/thread
    const int r0    = tid >> 3;                   // base row 0..63
    const int colel = (tid & 7) * 8;              // bf16 col within 64-col chunk
    uint32_t so[2];
#pragma unroll
    for (int i = 0; i < 2; i++) so[i] = swz((uint32_t)(r0 + 64 * i) * 128 + (tid & 7) * 16);

    const int nC = K >> 6;

    auto load_chunk = [&](int chunk, int buf) {
        const uint32_t sb = smem_base + buf * STAGE_BYTES;
        const long koff = (long)chunk * 64 + colel;
        const __nv_bfloat16* srcs[4] = {Ahi, Alo, Bhi, Blo};
        const int mn0[4] = {m0, m0, n0, n0};
#pragma unroll
        for (int t = 0; t < 4; t++) {
            const __nv_bfloat16* base = srcs[t] + (long)mn0[t] * K + koff;
            const uint32_t stb = sb + t * TILE_B;
#pragma unroll
            for (int i = 0; i < 2; i++)
                CP_ASYNC16(stb + so[i], base + (long)(r0 + 64 * i) * K);
        }
    };

    // --- ldmatrix lane geometry
    const int arow = (lane & 7) + ((lane >> 3) & 1) * 8;
    const uint32_t acol = ((lane >> 4) & 1) * 16;
    const int brow = (lane & 7) + ((lane >> 4) & 1) * 8;
    const uint32_t bcol = ((lane >> 3) & 1) * 16;
    uint32_t rA[2], rB[2];
#pragma unroll
    for (int mi = 0; mi < 2; mi++) rA[mi] = (uint32_t)(wm * 32 + mi * 16 + arow) * 128;
#pragma unroll
    for (int n2 = 0; n2 < 2; n2++) rB[n2] = (uint32_t)(wn * 32 + n2 * 16 + brow) * 128;

    float acc[2][4][4];
#pragma unroll
    for (int mi = 0; mi < 2; mi++)
#pragma unroll
        for (int ni = 0; ni < 4; ni++)
#pragma unroll
            for (int f = 0; f < 4; f++) acc[mi][ni][f] = 0.f;

    auto compute = [&](int buf) {
        const uint32_t sbA = smem_base + buf * STAGE_BYTES;
        const uint32_t sbB = sbA + 2 * TILE_B;
#pragma unroll
        for (int ks = 0; ks < 4; ks++) {
            uint32_t ah[2][4], al[2][4], bh[2][4], bl[2][4];
#pragma unroll
            for (int mi = 0; mi < 2; mi++) {
                LDSM_X4(ah[mi], sbA + swz(rA[mi] + ks * 32 + acol));
                LDSM_X4(al[mi], sbA + TILE_B + swz(rA[mi] + ks * 32 + acol));
            }
#pragma unroll
            for (int n2 = 0; n2 < 2; n2++) {
                LDSM_X4(bh[n2], sbB + swz(rB[n2] + ks * 32 + bcol));
                LDSM_X4(bl[n2], sbB + TILE_B + swz(rB[n2] + ks * 32 + bcol));
            }
            // pass 0: hi*hi
#pragma unroll
            for (int mi = 0; mi < 2; mi++)
#pragma unroll
                for (int ni = 0; ni < 4; ni++)
                    MMA16816(acc[mi][ni], ah[mi], (&bh[ni >> 1][(ni & 1) * 2]));
            // pass 1: hi*lo
#pragma unroll
            for (int mi = 0; mi < 2; mi++)
#pragma unroll
                for (int ni = 0; ni < 4; ni++)
                    MMA16816(acc[mi][ni], ah[mi], (&bl[ni >> 1][(ni & 1) * 2]));
            // pass 2: lo*hi
#pragma unroll
            for (int mi = 0; mi < 2; mi++)
#pragma unroll
                for (int ni = 0; ni < 4; ni++)
                    MMA16816(acc[mi][ni], al[mi], (&bh[ni >> 1][(ni & 1) * 2]));
        }
    };

    // --- pipeline
    load_chunk(0, 0); CP_COMMIT();
    load_chunk(1, 1); CP_COMMIT();

    for (int i = 0; i < nC; i++) {
        CP_WAIT1();
        __syncthreads();
        if (i + 2 < nC) load_chunk(i + 2, (i + 2) % STAGES);
        CP_COMMIT();
        compute(i % STAGES);
    }

    // --- epilogue ----------------------------------------------------------
    constexpr int TP = 136;   // padded row (elements) for the transpose tile
    __nv_bfloat16* Thi = (__nv_bfloat16*)smem_al;
    __nv_bfloat16* Tlo = Thi + 128 * TP;

    if (OUT_MODE == 2) __syncthreads();   // stage buffers are being repurposed

#pragma unroll
    for (int mi = 0; mi < 2; mi++) {
#pragma unroll
        for (int ni = 0; ni < 4; ni++) {
            const float* c = acc[mi][ni];
            const int mA = m0 + wm * 32 + mi * 16 + (lane >> 2);
            const int nA = n0 + wn * 32 + ni * 8 + (lane & 3) * 2;
#pragma unroll
            for (int h = 0; h < 2; h++) {
                const int m = mA + h * 8;
                float v0 = c[2 * h + 0] * scale;
                float v1 = c[2 * h + 1] * scale;
                if (HAS_BIAS) { v0 += bias[nA]; v1 += bias[nA + 1]; }
                if (MASK) {
                    float u0 = ((float)nA       - 0.5f * (float)N) / (0.25f * (float)N);
                    float u1 = ((float)(nA + 1) - 0.5f * (float)N) / (0.25f * (float)N);
                    v0 *= __expf(-0.5f * u0 * u0);
                    v1 *= __expf(-0.5f * u1 * u1);
                }
                if (OUT_MODE == 0) {
                    *(float2*)(Cf + (long)z * sC + (long)m * N + nA) = make_float2(v0, v1);
                } else if (OUT_MODE == 1) {
                    __nv_bfloat16 h0 = __float2bfloat16(v0);
                    __nv_bfloat16 h1 = __float2bfloat16(v1);
                    __nv_bfloat16 l0 = __float2bfloat16(v0 - __bfloat162float(h0));
                    __nv_bfloat16 l1 = __float2bfloat16(v1 - __bfloat162float(h1));
                    const long cb = (long)z * sC + (long)m * N + nA;
                    *(__nv_bfloat162*)(Chi + cb) = __nv_bfloat162(h0, h1);
                    *(__nv_bfloat162*)(Clo + cb) = __nv_bfloat162(l0, l1);
                } else {
                    // stage transposed into smem: T[n_local][m_local]
                    const int ml = m - m0;
                    const int nl0 = nA - n0;
                    __nv_bfloat16 h0 = __float2bfloat16(v0);
                    __nv_bfloat16 h1 = __float2bfloat16(v1);
                    __nv_bfloat16 l0 = __float2bfloat16(v0 - __bfloat162float(h0));
                    __nv_bfloat16 l1 = __float2bfloat16(v1 - __bfloat162float(h1));
                    Thi[nl0 * TP + ml]       = h0;
                    Thi[(nl0 + 1) * TP + ml] = h1;
                    Tlo[nl0 * TP + ml]       = l0;
                    Tlo[(nl0 + 1) * TP + ml] = l1;
                }
            }
        }
    }

    if (OUT_MODE == 2) {
        __syncthreads();
        // coalesced store: Vt[b][n][s]; CTA covers n in [n0,n0+128), s in [s0,s0+128)
        const int r = tid >> 2;               // 0..127 (local n)
        const int q4 = tid & 3;               // 0..3 -> 32-element quarters
        const long gb = ((long)(m0 >> 11) << 21) + ((long)(n0 + r) << 11)
                      + (long)(m0 & 2047) + q4 * 32;
        const uint4* sh = (const uint4*)(Thi + r * TP + q4 * 32);
        const uint4* sl = (const uint4*)(Tlo + r * TP + q4 * 32);
        uint4* dh = (uint4*)(Chi + gb);
        uint4* dl = (uint4*)(Clo + gb);
#pragma unroll
        for (int q = 0; q < 4; q++) dh[q] = sh[q];
#pragma unroll
        for (int q = 0; q < 4; q++) dl[q] = sl[q];
    }
}

// ===========================================================================
// fp32 -> bf16 hi/lo split conversion (single tensor)
// ===========================================================================
__device__ __forceinline__ void split_store(const float* s, __nv_bfloat16* hi,
                                            __nv_bfloat16* lo, long i) {
    float4 v = *(const float4*)(s + i * 4);
    __nv_bfloat16 h0 = __float2bfloat16(v.x), h1 = __float2bfloat16(v.y);
    __nv_bfloat16 h2 = __float2bfloat16(v.z), h3 = __float2bfloat16(v.w);
    __nv_bfloat16 l0 = __float2bfloat16(v.x - __bfloat162float(h0));
    __nv_bfloat16 l1 = __float2bfloat16(v.y - __bfloat162float(h1));
    __nv_bfloat16 l2 = __float2bfloat16(v.z - __bfloat162float(h2));
    __nv_bfloat16 l3 = __float2bfloat16(v.w - __bfloat162float(h3));
    *(__nv_bfloat162*)(hi + i * 4)     = __nv_bfloat162(h0, h1);
    *(__nv_bfloat162*)(hi + i * 4 + 2) = __nv_bfloat162(h2, h3);
    *(__nv_bfloat162*)(lo + i * 4)     = __nv_bfloat162(l0, l1);
    *(__nv_bfloat162*)(lo + i * 4 + 2) = __nv_bfloat162(l2, l3);
}

__global__ __launch_bounds__(256)
void split_f32(const float* __restrict__ s, __nv_bfloat16* __restrict__ hi,
               __nv_bfloat16* __restrict__ lo, long n4)
{
    long i = (long)blockIdx.x * blockDim.x + threadIdx.x;
    if (i >= n4) return;
    split_store(s, hi, lo, i);
}

// All four weight matrices in one launch (blockIdx.y selects the tensor)
__global__ __launch_bounds__(256)
void split_f32_w4(const float* __restrict__ w0, __nv_bfloat16* __restrict__ h0, __nv_bfloat16* __restrict__ l0,
                  const float* __restrict__ w1, __nv_bfloat16* __restrict__ h1, __nv_bfloat16* __restrict__ l1,
                  const float* __restrict__ w2, __nv_bfloat16* __restrict__ h2, __nv_bfloat16* __restrict__ l2,
                  const float* __restrict__ w3, __nv_bfloat16* __restrict__ h3, __nv_bfloat16* __restrict__ l3,
                  long n4)
{
    long i = (long)blockIdx.x * blockDim.x + threadIdx.x;
    if (i >= n4) return;
    const float* s;
    __nv_bfloat16 *hi, *lo;
    switch (blockIdx.y) {
        case 0: s = w0; hi = h0; lo = l0; break;
        case 1: s = w1; hi = h1; lo = l1; break;
        case 2: s = w2; hi = h2; lo = l2; break;
        default: s = w3; hi = h3; lo = l3; break;
    }
    split_store(s, hi, lo, i);
}

// ===========================================================================
// Row softmax (len 2048) fp32 in -> bf16 hi/lo split out
// ===========================================================================
__global__ __launch_bounds__(256)
void softmax_split(const float* __restrict__ P,
                   __nv_bfloat16* __restrict__ Phi, __nv_bfloat16* __restrict__ Plo)
{
    constexpr int VPT = Ss / 256;
    const float* p = P + (long)blockIdx.x * Ss;
    const long ob = (long)blockIdx.x * Ss;
    const int tid = threadIdx.x;

    float vals[VPT];
    float mx = -INFINITY;
#pragma unroll
    for (int i = 0; i < VPT; i++) { vals[i] = p[tid + i * 256]; mx = fmaxf(mx, vals[i]); }

    __shared__ float red[256];
    red[tid] = mx; __syncthreads();
    for (int s = 128; s > 0; s >>= 1) { if (tid < s) red[tid] = fmaxf(red[tid], red[tid + s]); __syncthreads(); }
    mx = red[0]; __syncthreads();

    float sum = 0.f;
#pragma unroll
    for (int i = 0; i < VPT; i++) { vals[i] = __expf(vals[i] - mx); sum += vals[i]; }
    red[tid] = sum; __syncthreads();
    for (int s = 128; s > 0; s >>= 1) { if (tid < s) red[tid] += red[tid + s]; __syncthreads(); }
    const float inv = 1.f / red[0];

#pragma unroll
    for (int i = 0; i < VPT; i++) {
        float v = vals[i] * inv;
        __nv_bfloat16 h = __float2bfloat16(v);
        __nv_bfloat16 l = __float2bfloat16(v - __bfloat162float(h));
        Phi[ob + tid + i * 256] = h;
        Plo[ob + tid + i * 256] = l;
    }
}

// ===========================================================================
extern "C" void kernel_launch(void* const* d_in, const int* in_sizes, int n_in,
                              void* d_out, int out_size)
{
    const float* x  = (const float*)d_in[0];
    const float* Wq = (const float*)d_in[1];
    const float* bq = (const float*)d_in[2];
    const float* Wk = (const float*)d_in[3];
    const float* bk = (const float*)d_in[4];
    const float* Wv = (const float*)d_in[5];
    const float* bv = (const float*)d_in[6];
    const float* Wo = (const float*)d_in[7];
    const float* bo = (const float*)d_in[8];
    float* out = (float*)d_out;

    __nv_bfloat16 *xhi, *xlo, *Wqhi, *Wqlo, *Wkhi, *Wklo, *Wvhi, *Wvlo, *Wohi, *Wolo;
    __nv_bfloat16 *Qhi, *Qlo, *Khi, *Klo, *Vthi, *Vtlo, *Phi, *Plo, *Ohi, *Olo;
    float* P;
    cudaGetSymbolAddress((void**)&xhi, g_xhi);   cudaGetSymbolAddress((void**)&xlo, g_xlo);
    cudaGetSymbolAddress((void**)&Wqhi, g_Wqhi); cudaGetSymbolAddress((void**)&Wqlo, g_Wqlo);
    cudaGetSymbolAddress((void**)&Wkhi, g_Wkhi); cudaGetSymbolAddress((void**)&Wklo, g_Wklo);
    cudaGetSymbolAddress((void**)&Wvhi, g_Wvhi); cudaGetSymbolAddress((void**)&Wvlo, g_Wvlo);
    cudaGetSymbolAddress((void**)&Wohi, g_Wohi); cudaGetSymbolAddress((void**)&Wolo, g_Wolo);
    cudaGetSymbolAddress((void**)&Qhi, g_Qhi);   cudaGetSymbolAddress((void**)&Qlo, g_Qlo);
    cudaGetSymbolAddress((void**)&Khi, g_Khi);   cudaGetSymbolAddress((void**)&Klo, g_Klo);
    cudaGetSymbolAddress((void**)&Vthi, g_Vthi); cudaGetSymbolAddress((void**)&Vtlo, g_Vtlo);
    cudaGetSymbolAddress((void**)&P, g_P);
    cudaGetSymbolAddress((void**)&Phi, g_Phi);   cudaGetSymbolAddress((void**)&Plo, g_Plo);
    cudaGetSymbolAddress((void**)&Ohi, g_Ohi);   cudaGetSymbolAddress((void**)&Olo, g_Olo);

    cudaFuncSetAttribute(hmma_gemm<1, true, false>,  cudaFuncAttributeMaxDynamicSharedMemorySize, SMEM_TOTAL);
    cudaFuncSetAttribute(hmma_gemm<2, true, false>,  cudaFuncAttributeMaxDynamicSharedMemorySize, SMEM_TOTAL);
    cudaFuncSetAttribute(hmma_gemm<0, false, true>,  cudaFuncAttributeMaxDynamicSharedMemorySize, SMEM_TOTAL);
    cudaFuncSetAttribute(hmma_gemm<1, false, false>, cudaFuncAttributeMaxDynamicSharedMemorySize, SMEM_TOTAL);
    cudaFuncSetAttribute(hmma_gemm<0, true, false>,  cudaFuncAttributeMaxDynamicSharedMemorySize, SMEM_TOTAL);

    // 1) split inputs (2 launches: x, then all 4 weights)
    split_f32<<<(MQ * Dd / 4 + 255) / 256, 256>>>(x, xhi, xlo, (long)MQ * Dd / 4);
    {
        dim3 gw((Dd * Dd / 4 + 255) / 256, 4, 1);
        split_f32_w4<<<gw, 256>>>(Wq, Wqhi, Wqlo, Wk, Wkhi, Wklo,
                                  Wv, Wvhi, Wvlo, Wo, Wohi, Wolo, (long)Dd * Dd / 4);
    }

    // 2) projections: Q, K (split layout), V (split + transposed to [b][d][s])
    dim3 gproj(Dd / 128, MQ / 128, 1);
    hmma_gemm<1, true, false><<<gproj, 512, SMEM_TOTAL>>>(
        xhi, xlo, Wqhi, Wqlo, bq, nullptr, Qhi, Qlo, MQ, Dd, Dd, 0, 0, 0, 1.f);
    hmma_gemm<1, true, false><<<gproj, 512, SMEM_TOTAL>>>(
        xhi, xlo, Wkhi, Wklo, bk, nullptr, Khi, Klo, MQ, Dd, Dd, 0, 0, 0, 1.f);
    hmma_gemm<2, true, false><<<gproj, 512, SMEM_TOTAL>>>(
        xhi, xlo, Wvhi, Wvlo, bv, nullptr, Vthi, Vtlo, MQ, Dd, Dd, 0, 0, 0, 1.f);

    // 3) scores = (Q @ K^T)/32 * mask(key)  -> fp32 P, batched  [ncu captures this]
    dim3 gsc(Ss / 128, Ss / 128, Bb);
    hmma_gemm<0, false, true><<<gsc, 512, SMEM_TOTAL>>>(
        Qhi, Qlo, Khi, Klo, nullptr, P, nullptr, nullptr,
        Ss, Ss, Dd, (long)Ss * Dd, (long)Ss * Dd, (long)Ss * Ss, 1.f / 32.f);

    // 4) softmax -> P split
    softmax_split<<<Bb * Ss, 256>>>(P, Phi, Plo);

    // 5) O = P @ Vt^T   (Vt rows are head-dims, K-contig over seq)
    dim3 gpv(Dd / 128, Ss / 128, Bb);
    hmma_gemm<1, false, false><<<gpv, 512, SMEM_TOTAL>>>(
        Phi, Plo, Vthi, Vtlo, nullptr, nullptr, Ohi, Olo,
        Ss, Dd, Ss, (long)Ss * Ss, (long)Dd * Ss, (long)Ss * Dd, 1.f);

    // 6) out = O @ Wo^T + bo  -> fp32
    hmma_gemm<0, true, false><<<gproj, 512, SMEM_TOTAL>>>(
        Ohi, Olo, Wohi, Wolo, bo, out, nullptr, nullptr, MQ, Dd, Dd, 0, 0, 0, 1.f);
}

// round 10
// speedup vs baseline: 2.0424x; 1.3169x over previous
#include <cuda_runtime.h>
#include <cuda_fp16.h>
#include <math.h>
#include <stdint.h>

// ===========================================================================
// Problem constants
// ===========================================================================
constexpr int Bb = 4;
constexpr int Ss = 2048;
constexpr int Dd = 1024;
constexpr int MQ = Bb * Ss;                 // 8192

// ===========================================================================
// Scratch (device globals; no allocation allowed)
// A-side operands need hi only; B-side operands need hi+lo.
// ===========================================================================
__device__ __half g_xh [(size_t)MQ * Dd];
__device__ __half g_Wqh[(size_t)Dd * Dd], g_Wql[(size_t)Dd * Dd];
__device__ __half g_Wkh[(size_t)Dd * Dd], g_Wkl[(size_t)Dd * Dd];
__device__ __half g_Wvh[(size_t)Dd * Dd], g_Wvl[(size_t)Dd * Dd];
__device__ __half g_Woh[(size_t)Dd * Dd], g_Wol[(size_t)Dd * Dd];
__device__ __half g_Qh [(size_t)MQ * Dd];                       // A-side (scores)
__device__ __half g_Kh [(size_t)MQ * Dd],  g_Kl [(size_t)MQ * Dd];   // B-side
__device__ __half g_Vth[(size_t)MQ * Dd],  g_Vtl[(size_t)MQ * Dd];   // B-side, [b][d][s]
__device__ float  g_P  [(size_t)Bb * Ss * Ss];
__device__ __half g_Ph [(size_t)Bb * Ss * Ss];                  // A-side (PV)
__device__ __half g_Oh [(size_t)MQ * Dd];                       // A-side (final)

// ===========================================================================
// Helpers (baseline sm_80+ instructions only; compute_103 has no tcgen05/TMA)
// ===========================================================================
__device__ __forceinline__ uint32_t smem_to_u32(const void* p) {
    uint32_t a;
    asm("{ .reg .u64 t; cvta.to.shared.u64 t, %1; cvt.u32.u64 %0, t; }" : "=r"(a) : "l"(p));
    return a;
}
__device__ __forceinline__ uint32_t swz(uint32_t b) { return b ^ ((b >> 3) & 0x70); }

#define CP_ASYNC16(smem_u32, gptr) \
    asm volatile("cp.async.cg.shared.global [%0], [%1], 16;" :: "r"(smem_u32), "l"(gptr) : "memory")
#define CP_COMMIT() asm volatile("cp.async.commit_group;" ::: "memory")
#define CP_WAIT1()  asm volatile("cp.async.wait_group 1;" ::: "memory")

#define LDSM_X4(r, addr) \
    asm volatile("ldmatrix.sync.aligned.m8n8.x4.shared.b16 {%0,%1,%2,%3}, [%4];" \
        : "=r"((r)[0]), "=r"((r)[1]), "=r"((r)[2]), "=r"((r)[3]) : "r"(addr))

#define MMA16816(d, a, b) \
    asm volatile("mma.sync.aligned.m16n8k16.row.col.f32.f16.f16.f32 " \
        "{%0,%1,%2,%3}, {%4,%5,%6,%7}, {%8,%9}, {%0,%1,%2,%3};" \
        : "+f"((d)[0]), "+f"((d)[1]), "+f"((d)[2]), "+f"((d)[3]) \
        : "r"((a)[0]), "r"((a)[1]), "r"((a)[2]), "r"((a)[3]), \
          "r"((b)[0]), "r"((b)[1]))

// ===========================================================================
// fp16 2-pass split GEMM:  C = (A @ B^T) * scale (+bias) (*gaussian mask)
//   C ≈ A_hi·B_hi + A_hi·B_lo       (A residual term dropped, ~2^-12 rel)
// A: [M,K] f16 row-major (hi only); B: [N,K] f16 hi/lo row-major.
// 512 threads, 16 warps 4x4, warp tile 32x32, CTA tile 128x128, BK=64.
// OUT_MODE: 0=fp32 C; 1=f16 hi-only C; 2=f16 hi+lo C; 3=f16 hi+lo V-transposed
// ===========================================================================
constexpr int STAGES = 3;
constexpr int TILE_B = 128 * 128;                  // 16 KB (128 rows x 64 f16)
constexpr int STAGE_BYTES = 3 * TILE_B;            // Ah, Bh, Bl = 48 KB
constexpr int SMEM_TOTAL = STAGES * STAGE_BYTES + 1024;   // ~145 KB

template <int OUT_MODE, bool HAS_BIAS, bool MASK>
__global__ __launch_bounds__(512, 1)
void hgemm(const __half* __restrict__ Ah,
           const __half* __restrict__ Bh, const __half* __restrict__ Bl,
           const float* __restrict__ bias,
           float* __restrict__ Cf,
           __half* __restrict__ Chi, __half* __restrict__ Clo,
           int M, int N, int K, long sA, long sB, long sC, float scale)
{
    extern __shared__ char smem[];
    char* smem_al = (char*)(((uintptr_t)smem + 1023ull) & ~1023ull);
    const uint32_t smem_base = smem_to_u32(smem_al);

    const int tid = threadIdx.x, wid = tid >> 5, lane = tid & 31;
    const int m0 = blockIdx.y * 128, n0 = blockIdx.x * 128;
    const int z = blockIdx.z;
    const int wm = wid >> 2, wn = wid & 3;        // warp tile: 32x32

    Ah += (long)z * sA;
    Bh += (long)z * sB;  Bl += (long)z * sB;

    // --- cp.async geometry: 16KB tile = 1024 x 16B chunks; 2 chunks/thread/tile
    const int r0    = tid >> 3;                   // base row 0..63
    const int colel = (tid & 7) * 8;              // f16 col within 64-col chunk
    uint32_t so[2];
#pragma unroll
    for (int i = 0; i < 2; i++) so[i] = swz((uint32_t)(r0 + 64 * i) * 128 + (tid & 7) * 16);

    const int nC = K >> 6;

    auto load_chunk = [&](int chunk, int buf) {
        const uint32_t sb = smem_base + buf * STAGE_BYTES;
        const long koff = (long)chunk * 64 + colel;
        const __half* srcs[3] = {Ah, Bh, Bl};
        const int mn0[3] = {m0, n0, n0};
#pragma unroll
        for (int t = 0; t < 3; t++) {
            const __half* base = srcs[t] + (long)mn0[t] * K + koff;
            const uint32_t stb = sb + t * TILE_B;
#pragma unroll
            for (int i = 0; i < 2; i++)
                CP_ASYNC16(stb + so[i], base + (long)(r0 + 64 * i) * K);
        }
    };

    // --- ldmatrix lane geometry
    const int arow = (lane & 7) + ((lane >> 3) & 1) * 8;
    const uint32_t acol = ((lane >> 4) & 1) * 16;
    const int brow = (lane & 7) + ((lane >> 4) & 1) * 8;
    const uint32_t bcol = ((lane >> 3) & 1) * 16;
    uint32_t rA[2], rB[2];
#pragma unroll
    for (int mi = 0; mi < 2; mi++) rA[mi] = (uint32_t)(wm * 32 + mi * 16 + arow) * 128;
#pragma unroll
    for (int n2 = 0; n2 < 2; n2++) rB[n2] = (uint32_t)(wn * 32 + n2 * 16 + brow) * 128;

    float acc[2][4][4];
#pragma unroll
    for (int mi = 0; mi < 2; mi++)
#pragma unroll
        for (int ni = 0; ni < 4; ni++)
#pragma unroll
            for (int f = 0; f < 4; f++) acc[mi][ni][f] = 0.f;

    auto compute = [&](int buf) {
        const uint32_t sbA = smem_base + buf * STAGE_BYTES;
        const uint32_t sbB = sbA + TILE_B;        // B_hi
        const uint32_t sbL = sbA + 2 * TILE_B;    // B_lo
#pragma unroll
        for (int ks = 0; ks < 4; ks++) {
            uint32_t ah[2][4], bh[2][4], bl[2][4];
#pragma unroll
            for (int mi = 0; mi < 2; mi++)
                LDSM_X4(ah[mi], sbA + swz(rA[mi] + ks * 32 + acol));
#pragma unroll
            for (int n2 = 0; n2 < 2; n2++) {
                LDSM_X4(bh[n2], sbB + swz(rB[n2] + ks * 32 + bcol));
                LDSM_X4(bl[n2], sbL + swz(rB[n2] + ks * 32 + bcol));
            }
            // pass 0: A_hi * B_hi
#pragma unroll
            for (int mi = 0; mi < 2; mi++)
#pragma unroll
                for (int ni = 0; ni < 4; ni++)
                    MMA16816(acc[mi][ni], ah[mi], (&bh[ni >> 1][(ni & 1) * 2]));
            // pass 1: A_hi * B_lo
#pragma unroll
            for (int mi = 0; mi < 2; mi++)
#pragma unroll
                for (int ni = 0; ni < 4; ni++)
                    MMA16816(acc[mi][ni], ah[mi], (&bl[ni >> 1][(ni & 1) * 2]));
        }
    };

    // --- pipeline
    load_chunk(0, 0); CP_COMMIT();
    load_chunk(1, 1); CP_COMMIT();

    for (int i = 0; i < nC; i++) {
        CP_WAIT1();
        __syncthreads();
        if (i + 2 < nC) load_chunk(i + 2, (i + 2) % STAGES);
        CP_COMMIT();
        compute(i % STAGES);
    }

    // --- epilogue ----------------------------------------------------------
    constexpr int TP = 136;   // padded row (elements) for the transpose tile
    __half* Thi = (__half*)smem_al;
    __half* Tlo = Thi + 128 * TP;

    if (OUT_MODE == 3) __syncthreads();   // stage buffers repurposed

#pragma unroll
    for (int mi = 0; mi < 2; mi++) {
#pragma unroll
        for (int ni = 0; ni < 4; ni++) {
            const float* c = acc[mi][ni];
            const int mA = m0 + wm * 32 + mi * 16 + (lane >> 2);
            const int nA = n0 + wn * 32 + ni * 8 + (lane & 3) * 2;
#pragma unroll
            for (int h = 0; h < 2; h++) {
                const int m = mA + h * 8;
                float v0 = c[2 * h + 0] * scale;
                float v1 = c[2 * h + 1] * scale;
                if (HAS_BIAS) { v0 += bias[nA]; v1 += bias[nA + 1]; }
                if (MASK) {
                    float u0 = ((float)nA       - 0.5f * (float)N) / (0.25f * (float)N);
                    float u1 = ((float)(nA + 1) - 0.5f * (float)N) / (0.25f * (float)N);
                    v0 *= __expf(-0.5f * u0 * u0);
                    v1 *= __expf(-0.5f * u1 * u1);
                }
                if (OUT_MODE == 0) {
                    *(float2*)(Cf + (long)z * sC + (long)m * N + nA) = make_float2(v0, v1);
                } else if (OUT_MODE == 1) {
                    const long cb = (long)z * sC + (long)m * N + nA;
                    *(__half2*)(Chi + cb) = __halves2half2(__float2half(v0), __float2half(v1));
                } else if (OUT_MODE == 2) {
                    __half h0 = __float2half(v0);
                    __half h1 = __float2half(v1);
                    __half l0 = __float2half(v0 - __half2float(h0));
                    __half l1 = __float2half(v1 - __half2float(h1));
                    const long cb = (long)z * sC + (long)m * N + nA;
                    *(__half2*)(Chi + cb) = __halves2half2(h0, h1);
                    *(__half2*)(Clo + cb) = __halves2half2(l0, l1);
                } else {
                    // stage transposed into smem: T[n_local][m_local]
                    const int ml = m - m0;
                    const int nl0 = nA - n0;
                    __half h0 = __float2half(v0);
                    __half h1 = __float2half(v1);
                    __half l0 = __float2half(v0 - __half2float(h0));
                    __half l1 = __float2half(v1 - __half2float(h1));
                    Thi[nl0 * TP + ml]       = h0;
                    Thi[(nl0 + 1) * TP + ml] = h1;
                    Tlo[nl0 * TP + ml]       = l0;
                    Tlo[(nl0 + 1) * TP + ml] = l1;
                }
            }
        }
    }

    if (OUT_MODE == 3) {
        __syncthreads();
        // coalesced store: Vt[b][n][s]; CTA covers n in [n0,n0+128), s in [m0..m0+128)
        const int r = tid >> 2;               // 0..127 (local n)
        const int q4 = tid & 3;               // 0..3 -> 32-element quarters
        const long gb = ((long)(m0 >> 11) << 21) + ((long)(n0 + r) << 11)
                      + (long)(m0 & 2047) + q4 * 32;
        const uint4* sh = (const uint4*)(Thi + r * TP + q4 * 32);
        const uint4* sl = (const uint4*)(Tlo + r * TP + q4 * 32);
        uint4* dh = (uint4*)(Chi + gb);
        uint4* dl = (uint4*)(Clo + gb);
#pragma unroll
        for (int q = 0; q < 4; q++) dh[q] = sh[q];
#pragma unroll
        for (int q = 0; q < 4; q++) dl[q] = sl[q];
    }
}

// ===========================================================================
// fp32 -> f16 conversions
// ===========================================================================
__global__ __launch_bounds__(256)
void conv_h(const float* __restrict__ s, __half* __restrict__ hi, long n4)
{
    long i = (long)blockIdx.x * blockDim.x + threadIdx.x;
    if (i >= n4) return;
    float4 v = *(const float4*)(s + i * 4);
    *(__half2*)(hi + i * 4)     = __halves2half2(__float2half(v.x), __float2half(v.y));
    *(__half2*)(hi + i * 4 + 2) = __halves2half2(__float2half(v.z), __float2half(v.w));
}

// All four weight matrices hi+lo in one launch (blockIdx.y selects the tensor)
__global__ __launch_bounds__(256)
void split_w4(const float* __restrict__ w0, __half* __restrict__ h0, __half* __restrict__ l0,
              const float* __restrict__ w1, __half* __restrict__ h1, __half* __restrict__ l1,
              const float* __restrict__ w2, __half* __restrict__ h2, __half* __restrict__ l2,
              const float* __restrict__ w3, __half* __restrict__ h3, __half* __restrict__ l3,
              long n4)
{
    long i = (long)blockIdx.x * blockDim.x + threadIdx.x;
    if (i >= n4) return;
    const float* s;
    __half *hi, *lo;
    switch (blockIdx.y) {
        case 0: s = w0; hi = h0; lo = l0; break;
        case 1: s = w1; hi = h1; lo = l1; break;
        case 2: s = w2; hi = h2; lo = l2; break;
        default: s = w3; hi = h3; lo = l3; break;
    }
    float4 v = *(const float4*)(s + i * 4);
    __half a0 = __float2half(v.x), a1 = __float2half(v.y);
    __half a2 = __float2half(v.z), a3 = __float2half(v.w);
    __half b0 = __float2half(v.x - __half2float(a0));
    __half b1 = __float2half(v.y - __half2float(a1));
    __half b2 = __float2half(v.z - __half2float(a2));
    __half b3 = __float2half(v.w - __half2float(a3));
    *(__half2*)(hi + i * 4)     = __halves2half2(a0, a1);
    *(__half2*)(hi + i * 4 + 2) = __halves2half2(a2, a3);
    *(__half2*)(lo + i * 4)     = __halves2half2(b0, b1);
    *(__half2*)(lo + i * 4 + 2) = __halves2half2(b2, b3);
}

// ===========================================================================
// Row softmax (len 2048) fp32 in -> f16 hi out
// ===========================================================================
__global__ __launch_bounds__(256)
void softmax_h(const float* __restrict__ P, __half* __restrict__ Ph)
{
    constexpr int VPT = Ss / 256;
    const float* p = P + (long)blockIdx.x * Ss;
    const long ob = (long)blockIdx.x * Ss;
    const int tid = threadIdx.x;

    float vals[VPT];
    float mx = -INFINITY;
#pragma unroll
    for (int i = 0; i < VPT; i++) { vals[i] = p[tid + i * 256]; mx = fmaxf(mx, vals[i]); }

    __shared__ float red[256];
    red[tid] = mx; __syncthreads();
    for (int s = 128; s > 0; s >>= 1) { if (tid < s) red[tid] = fmaxf(red[tid], red[tid + s]); __syncthreads(); }
    mx = red[0]; __syncthreads();

    float sum = 0.f;
#pragma unroll
    for (int i = 0; i < VPT; i++) { vals[i] = __expf(vals[i] - mx); sum += vals[i]; }
    red[tid] = sum; __syncthreads();
    for (int s = 128; s > 0; s >>= 1) { if (tid < s) red[tid] += red[tid + s]; __syncthreads(); }
    const float inv = 1.f / red[0];

#pragma unroll
    for (int i = 0; i < VPT; i++)
        Ph[ob + tid + i * 256] = __float2half(vals[i] * inv);
}

// ===========================================================================
extern "C" void kernel_launch(void* const* d_in, const int* in_sizes, int n_in,
                              void* d_out, int out_size)
{
    const float* x  = (const float*)d_in[0];
    const float* Wq = (const float*)d_in[1];
    const float* bq = (const float*)d_in[2];
    const float* Wk = (const float*)d_in[3];
    const float* bk = (const float*)d_in[4];
    const float* Wv = (const float*)d_in[5];
    const float* bv = (const float*)d_in[6];
    const float* Wo = (const float*)d_in[7];
    const float* bo = (const float*)d_in[8];
    float* out = (float*)d_out;

    __half *xh, *Wqh, *Wql, *Wkh, *Wkl, *Wvh, *Wvl, *Woh, *Wol;
    __half *Qh, *Kh, *Kl, *Vth, *Vtl, *Ph, *Oh;
    float* P;
    cudaGetSymbolAddress((void**)&xh, g_xh);
    cudaGetSymbolAddress((void**)&Wqh, g_Wqh); cudaGetSymbolAddress((void**)&Wql, g_Wql);
    cudaGetSymbolAddress((void**)&Wkh, g_Wkh); cudaGetSymbolAddress((void**)&Wkl, g_Wkl);
    cudaGetSymbolAddress((void**)&Wvh, g_Wvh); cudaGetSymbolAddress((void**)&Wvl, g_Wvl);
    cudaGetSymbolAddress((void**)&Woh, g_Woh); cudaGetSymbolAddress((void**)&Wol, g_Wol);
    cudaGetSymbolAddress((void**)&Qh, g_Qh);
    cudaGetSymbolAddress((void**)&Kh, g_Kh);   cudaGetSymbolAddress((void**)&Kl, g_Kl);
    cudaGetSymbolAddress((void**)&Vth, g_Vth); cudaGetSymbolAddress((void**)&Vtl, g_Vtl);
    cudaGetSymbolAddress((void**)&P, g_P);
    cudaGetSymbolAddress((void**)&Ph, g_Ph);
    cudaGetSymbolAddress((void**)&Oh, g_Oh);

    cudaFuncSetAttribute(hgemm<1, true, false>,  cudaFuncAttributeMaxDynamicSharedMemorySize, SMEM_TOTAL);
    cudaFuncSetAttribute(hgemm<2, true, false>,  cudaFuncAttributeMaxDynamicSharedMemorySize, SMEM_TOTAL);
    cudaFuncSetAttribute(hgemm<3, true, false>,  cudaFuncAttributeMaxDynamicSharedMemorySize, SMEM_TOTAL);
    cudaFuncSetAttribute(hgemm<0, false, true>,  cudaFuncAttributeMaxDynamicSharedMemorySize, SMEM_TOTAL);
    cudaFuncSetAttribute(hgemm<1, false, false>, cudaFuncAttributeMaxDynamicSharedMemorySize, SMEM_TOTAL);
    cudaFuncSetAttribute(hgemm<0, true, false>,  cudaFuncAttributeMaxDynamicSharedMemorySize, SMEM_TOTAL);

    // 1) conversions: x (hi only), W's (hi+lo)
    conv_h<<<(MQ * Dd / 4 + 255) / 256, 256>>>(x, xh, (long)MQ * Dd / 4);
    {
        dim3 gw((Dd * Dd / 4 + 255) / 256, 4, 1);
        split_w4<<<gw, 256>>>(Wq, Wqh, Wql, Wk, Wkh, Wkl,
                              Wv, Wvh, Wvl, Wo, Woh, Wol, (long)Dd * Dd / 4);
    }

    // 2) projections
    dim3 gproj(Dd / 128, MQ / 128, 1);
    hgemm<1, true, false><<<gproj, 512, SMEM_TOTAL>>>(
        xh, Wqh, Wql, bq, nullptr, Qh, nullptr, MQ, Dd, Dd, 0, 0, 0, 1.f);
    hgemm<2, true, false><<<gproj, 512, SMEM_TOTAL>>>(
        xh, Wkh, Wkl, bk, nullptr, Kh, Kl, MQ, Dd, Dd, 0, 0, 0, 1.f);
    hgemm<3, true, false><<<gproj, 512, SMEM_TOTAL>>>(
        xh, Wvh, Wvl, bv, nullptr, Vth, Vtl, MQ, Dd, Dd, 0, 0, 0, 1.f);

    // 3) scores = (Q @ K^T)/32 * mask(key) -> fp32 P, batched  [ncu captures this]
    dim3 gsc(Ss / 128, Ss / 128, Bb);
    hgemm<0, false, true><<<gsc, 512, SMEM_TOTAL>>>(
        Qh, Kh, Kl, nullptr, P, nullptr, nullptr,
        Ss, Ss, Dd, (long)Ss * Dd, (long)Ss * Dd, (long)Ss * Ss, 1.f / 32.f);

    // 4) softmax -> P hi
    softmax_h<<<Bb * Ss, 256>>>(P, Ph);

    // 5) O = P @ Vt^T
    dim3 gpv(Dd / 128, Ss / 128, Bb);
    hgemm<1, false, false><<<gpv, 512, SMEM_TOTAL>>>(
        Ph, Vth, Vtl, nullptr, nullptr, Oh, nullptr,
        Ss, Dd, Ss, (long)Ss * Ss, (long)Dd * Ss, (long)Ss * Dd, 1.f);

    // 6) out = O @ Wo^T + bo -> fp32
    hgemm<0, true, false><<<gproj, 512, SMEM_TOTAL>>>(
        Oh, Woh, Wol, bo, out, nullptr, nullptr, MQ, Dd, Dd, 0, 0, 0, 1.f);
}

// round 12
// speedup vs baseline: 2.2210x; 1.0874x over previous
#include <cuda_runtime.h>
#include <cuda_fp16.h>
#include <math.h>
#include <stdint.h>

// Resubmission of R11 kernel — previous round failed in infra (container), not bench.

// ===========================================================================
// Problem constants
// ===========================================================================
constexpr int Bb = 4;
constexpr int Ss = 2048;
constexpr int Dd = 1024;
constexpr int MQ = Bb * Ss;                 // 8192

// ===========================================================================
// Scratch (device globals; no allocation allowed)
// A-side operands need hi only; B-side operands need hi+lo.
// ===========================================================================
__device__ __half g_xh [(size_t)MQ * Dd];
__device__ __half g_Wqh[(size_t)Dd * Dd], g_Wql[(size_t)Dd * Dd];
__device__ __half g_Wkh[(size_t)Dd * Dd], g_Wkl[(size_t)Dd * Dd];
__device__ __half g_Wvh[(size_t)Dd * Dd], g_Wvl[(size_t)Dd * Dd];
__device__ __half g_Woh[(size_t)Dd * Dd], g_Wol[(size_t)Dd * Dd];
__device__ __half g_Qh [(size_t)MQ * Dd];                       // A-side (scores)
__device__ __half g_Kh [(size_t)MQ * Dd],  g_Kl [(size_t)MQ * Dd];   // B-side
__device__ __half g_Vth[(size_t)MQ * Dd],  g_Vtl[(size_t)MQ * Dd];   // B-side, [b][d][s]
__device__ float  g_P  [(size_t)Bb * Ss * Ss];
__device__ __half g_Ph [(size_t)Bb * Ss * Ss];                  // A-side (PV)
__device__ __half g_Oh [(size_t)MQ * Dd];                       // A-side (final)

// ===========================================================================
// Helpers (baseline sm_80+ instructions only; compute_103 has no tcgen05/TMA)
// ===========================================================================
__device__ __forceinline__ uint32_t smem_to_u32(const void* p) {
    uint32_t a;
    asm("{ .reg .u64 t; cvta.to.shared.u64 t, %1; cvt.u32.u64 %0, t; }" : "=r"(a) : "l"(p));
    return a;
}
__device__ __forceinline__ uint32_t swz(uint32_t b) { return b ^ ((b >> 3) & 0x70); }

#define CP_ASYNC16(smem_u32, gptr) \
    asm volatile("cp.async.cg.shared.global [%0], [%1], 16;" :: "r"(smem_u32), "l"(gptr) : "memory")
#define CP_COMMIT() asm volatile("cp.async.commit_group;" ::: "memory")
#define CP_WAIT1()  asm volatile("cp.async.wait_group 1;" ::: "memory")

#define LDSM_X4(r, addr) \
    asm volatile("ldmatrix.sync.aligned.m8n8.x4.shared.b16 {%0,%1,%2,%3}, [%4];" \
        : "=r"((r)[0]), "=r"((r)[1]), "=r"((r)[2]), "=r"((r)[3]) : "r"(addr))

#define MMA16816(d, a, b) \
    asm volatile("mma.sync.aligned.m16n8k16.row.col.f32.f16.f16.f32 " \
        "{%0,%1,%2,%3}, {%4,%5,%6,%7}, {%8,%9}, {%0,%1,%2,%3};" \
        : "+f"((d)[0]), "+f"((d)[1]), "+f"((d)[2]), "+f"((d)[3]) \
        : "r"((a)[0]), "r"((a)[1]), "r"((a)[2]), "r"((a)[3]), \
          "r"((b)[0]), "r"((b)[1]))

// ===========================================================================
// fp16 2-pass split GEMM:  C = (A @ B^T) * scale (+bias) (*gaussian mask)
//   C ≈ A_hi·B_hi + A_hi·B_lo
// CTA tile 256x128, BK=64; 512 threads = 16 warps (4x4), warp tile 64x32.
// OUT_MODE: 0=fp32 C; 1=f16 hi-only C; 2=f16 hi+lo C; 3=f16 hi+lo V-transposed
// ===========================================================================
constexpr int STAGES = 3;
constexpr int TILE_A  = 256 * 128;                 // 32 KB (256 rows x 64 f16)
constexpr int TILE_Bh = 128 * 128;                 // 16 KB
constexpr int STAGE_BYTES = TILE_A + 2 * TILE_Bh;  // 64 KB
constexpr int SMEM_TOTAL = STAGES * STAGE_BYTES + 1024;   // ~193 KB

template <int OUT_MODE, bool HAS_BIAS, bool MASK>
__global__ __launch_bounds__(512, 1)
void hgemm(const __half* __restrict__ Ah,
           const __half* __restrict__ Bh, const __half* __restrict__ Bl,
           const float* __restrict__ bias,
           float* __restrict__ Cf,
           __half* __restrict__ Chi, __half* __restrict__ Clo,
           int M, int N, int K, long sA, long sB, long sC, float scale)
{
    extern __shared__ char smem[];
    char* smem_al = (char*)(((uintptr_t)smem + 1023ull) & ~1023ull);
    const uint32_t smem_base = smem_to_u32(smem_al);

    const int tid = threadIdx.x, wid = tid >> 5, lane = tid & 31;
    const int m0 = blockIdx.y * 256, n0 = blockIdx.x * 128;
    const int z = blockIdx.z;
    const int wm = wid >> 2, wn = wid & 3;        // warp tile: 64x32

    Ah += (long)z * sA;
    Bh += (long)z * sB;  Bl += (long)z * sB;

    // --- cp.async geometry: A = 2048 16B chunks (4/thread); each B = 1024 (2/thread)
    const int r0    = tid >> 3;                   // base row 0..63
    const int colel = (tid & 7) * 8;              // f16 col within 64-col chunk
    uint32_t so[4];
#pragma unroll
    for (int i = 0; i < 4; i++) so[i] = swz((uint32_t)(r0 + 64 * i) * 128 + (tid & 7) * 16);

    const int nC = K >> 6;

    auto load_chunk = [&](int chunk, int buf) {
        const uint32_t sb = smem_base + buf * STAGE_BYTES;
        const long koff = (long)chunk * 64 + colel;
        {   // A: 256 rows
            const __half* base = Ah + (long)m0 * K + koff;
#pragma unroll
            for (int i = 0; i < 4; i++)
                CP_ASYNC16(sb + so[i], base + (long)(r0 + 64 * i) * K);
        }
        {   // B hi: 128 rows
            const __half* base = Bh + (long)n0 * K + koff;
            const uint32_t stb = sb + TILE_A;
#pragma unroll
            for (int i = 0; i < 2; i++)
                CP_ASYNC16(stb + so[i], base + (long)(r0 + 64 * i) * K);
        }
        {   // B lo: 128 rows
            const __half* base = Bl + (long)n0 * K + koff;
            const uint32_t stb = sb + TILE_A + TILE_Bh;
#pragma unroll
            for (int i = 0; i < 2; i++)
                CP_ASYNC16(stb + so[i], base + (long)(r0 + 64 * i) * K);
        }
    };

    // --- ldmatrix lane geometry
    const int arow = (lane & 7) + ((lane >> 3) & 1) * 8;
    const uint32_t acol = ((lane >> 4) & 1) * 16;
    const int brow = (lane & 7) + ((lane >> 4) & 1) * 8;
    const uint32_t bcol = ((lane >> 3) & 1) * 16;
    uint32_t rA[4], rB[2];
#pragma unroll
    for (int mi = 0; mi < 4; mi++) rA[mi] = (uint32_t)(wm * 64 + mi * 16 + arow) * 128;
#pragma unroll
    for (int n2 = 0; n2 < 2; n2++) rB[n2] = (uint32_t)(wn * 32 + n2 * 16 + brow) * 128;

    float acc[4][4][4];
#pragma unroll
    for (int mi = 0; mi < 4; mi++)
#pragma unroll
        for (int ni = 0; ni < 4; ni++)
#pragma unroll
            for (int f = 0; f < 4; f++) acc[mi][ni][f] = 0.f;

    auto compute = [&](int buf) {
        const uint32_t sbA = smem_base + buf * STAGE_BYTES;
        const uint32_t sbB = sbA + TILE_A;        // B_hi
        const uint32_t sbL = sbB + TILE_Bh;       // B_lo
#pragma unroll
        for (int ks = 0; ks < 4; ks++) {
            uint32_t ah[4][4], bh[2][4], bl[2][4];
#pragma unroll
            for (int mi = 0; mi < 4; mi++)
                LDSM_X4(ah[mi], sbA + swz(rA[mi] + ks * 32 + acol));
#pragma unroll
            for (int n2 = 0; n2 < 2; n2++) {
                LDSM_X4(bh[n2], sbB + swz(rB[n2] + ks * 32 + bcol));
                LDSM_X4(bl[n2], sbL + swz(rB[n2] + ks * 32 + bcol));
            }
            // pass 0: A_hi * B_hi
#pragma unroll
            for (int mi = 0; mi < 4; mi++)
#pragma unroll
                for (int ni = 0; ni < 4; ni++)
                    MMA16816(acc[mi][ni], ah[mi], (&bh[ni >> 1][(ni & 1) * 2]));
            // pass 1: A_hi * B_lo
#pragma unroll
            for (int mi = 0; mi < 4; mi++)
#pragma unroll
                for (int ni = 0; ni < 4; ni++)
                    MMA16816(acc[mi][ni], ah[mi], (&bl[ni >> 1][(ni & 1) * 2]));
        }
    };

    // --- pipeline
    load_chunk(0, 0); CP_COMMIT();
    load_chunk(1, 1); CP_COMMIT();

    for (int i = 0; i < nC; i++) {
        CP_WAIT1();
        __syncthreads();
        if (i + 2 < nC) load_chunk(i + 2, (i + 2) % STAGES);
        CP_COMMIT();
        compute(i % STAGES);
    }

    // --- epilogue ----------------------------------------------------------
    constexpr int TP = 264;   // padded row (elements) for the transpose tile (256+8)
    __half* Thi = (__half*)smem_al;
    __half* Tlo = Thi + 128 * TP;

    if (OUT_MODE == 3) __syncthreads();   // stage buffers repurposed

#pragma unroll
    for (int mi = 0; mi < 4; mi++) {
#pragma unroll
        for (int ni = 0; ni < 4; ni++) {
            const float* c = acc[mi][ni];
            const int mA = m0 + wm * 64 + mi * 16 + (lane >> 2);
            const int nA = n0 + wn * 32 + ni * 8 + (lane & 3) * 2;
#pragma unroll
            for (int h = 0; h < 2; h++) {
                const int m = mA + h * 8;
                float v0 = c[2 * h + 0] * scale;
                float v1 = c[2 * h + 1] * scale;
                if (HAS_BIAS) { v0 += bias[nA]; v1 += bias[nA + 1]; }
                if (MASK) {
                    float u0 = ((float)nA       - 0.5f * (float)N) / (0.25f * (float)N);
                    float u1 = ((float)(nA + 1) - 0.5f * (float)N) / (0.25f * (float)N);
                    v0 *= __expf(-0.5f * u0 * u0);
                    v1 *= __expf(-0.5f * u1 * u1);
                }
                if (OUT_MODE == 0) {
                    *(float2*)(Cf + (long)z * sC + (long)m * N + nA) = make_float2(v0, v1);
                } else if (OUT_MODE == 1) {
                    const long cb = (long)z * sC + (long)m * N + nA;
                    *(__half2*)(Chi + cb) = __halves2half2(__float2half(v0), __float2half(v1));
                } else if (OUT_MODE == 2) {
                    __half h0 = __float2half(v0);
                    __half h1 = __float2half(v1);
                    __half l0 = __float2half(v0 - __half2float(h0));
                    __half l1 = __float2half(v1 - __half2float(h1));
                    const long cb = (long)z * sC + (long)m * N + nA;
                    *(__half2*)(Chi + cb) = __halves2half2(h0, h1);
                    *(__half2*)(Clo + cb) = __halves2half2(l0, l1);
                } else {
                    // stage transposed into smem: T[n_local][m_local]
                    const int ml = m - m0;
                    const int nl0 = nA - n0;
                    __half h0 = __float2half(v0);
                    __half h1 = __float2half(v1);
                    __half l0 = __float2half(v0 - __half2float(h0));
                    __half l1 = __float2half(v1 - __half2float(h1));
                    Thi[nl0 * TP + ml]       = h0;
                    Thi[(nl0 + 1) * TP + ml] = h1;
                    Tlo[nl0 * TP + ml]       = l0;
                    Tlo[(nl0 + 1) * TP + ml] = l1;
                }
            }
        }
    }

    if (OUT_MODE == 3) {
        __syncthreads();
        // coalesced store: Vt[b][n][s]; CTA covers n in [n0,n0+128), s in [m0,m0+256)
        const int r = tid >> 2;               // 0..127 (local n)
        const int q4 = tid & 3;               // 0..3 -> 64-element quarters of 256
        const long gb = ((long)(m0 >> 11) << 21) + ((long)(n0 + r) << 11)
                      + (long)(m0 & 2047) + q4 * 64;
        const uint4* sh = (const uint4*)(Thi + r * TP + q4 * 64);
        const uint4* sl = (const uint4*)(Tlo + r * TP + q4 * 64);
        uint4* dh = (uint4*)(Chi + gb);
        uint4* dl = (uint4*)(Clo + gb);
#pragma unroll
        for (int q = 0; q < 8; q++) dh[q] = sh[q];
#pragma unroll
        for (int q = 0; q < 8; q++) dl[q] = sl[q];
    }
}

// ===========================================================================
// fp32 -> f16 conversions
// ===========================================================================
__global__ __launch_bounds__(256)
void conv_h(const float* __restrict__ s, __half* __restrict__ hi, long n4)
{
    long i = (long)blockIdx.x * blockDim.x + threadIdx.x;
    if (i >= n4) return;
    float4 v = *(const float4*)(s + i * 4);
    *(__half2*)(hi + i * 4)     = __halves2half2(__float2half(v.x), __float2half(v.y));
    *(__half2*)(hi + i * 4 + 2) = __halves2half2(__float2half(v.z), __float2half(v.w));
}

// All four weight matrices hi+lo in one launch (blockIdx.y selects the tensor)
__global__ __launch_bounds__(256)
void split_w4(const float* __restrict__ w0, __half* __restrict__ h0, __half* __restrict__ l0,
              const float* __restrict__ w1, __half* __restrict__ h1, __half* __restrict__ l1,
              const float* __restrict__ w2, __half* __restrict__ h2, __half* __restrict__ l2,
              const float* __restrict__ w3, __half* __restrict__ h3, __half* __restrict__ l3,
              long n4)
{
    long i = (long)blockIdx.x * blockDim.x + threadIdx.x;
    if (i >= n4) return;
    const float* s;
    __half *hi, *lo;
    switch (blockIdx.y) {
        case 0: s = w0; hi = h0; lo = l0; break;
        case 1: s = w1; hi = h1; lo = l1; break;
        case 2: s = w2; hi = h2; lo = l2; break;
        default: s = w3; hi = h3; lo = l3; break;
    }
    float4 v = *(const float4*)(s + i * 4);
    __half a0 = __float2half(v.x), a1 = __float2half(v.y);
    __half a2 = __float2half(v.z), a3 = __float2half(v.w);
    __half b0 = __float2half(v.x - __half2float(a0));
    __half b1 = __float2half(v.y - __half2float(a1));
    __half b2 = __float2half(v.z - __half2float(a2));
    __half b3 = __float2half(v.w - __half2float(a3));
    *(__half2*)(hi + i * 4)     = __halves2half2(a0, a1);
    *(__half2*)(hi + i * 4 + 2) = __halves2half2(a2, a3);
    *(__half2*)(lo + i * 4)     = __halves2half2(b0, b1);
    *(__half2*)(lo + i * 4 + 2) = __halves2half2(b2, b3);
}

// ===========================================================================
// Row softmax (len 2048) fp32 in -> f16 hi out
// ===========================================================================
__global__ __launch_bounds__(256)
void softmax_h(const float* __restrict__ P, __half* __restrict__ Ph)
{
    constexpr int VPT = Ss / 256;
    const float* p = P + (long)blockIdx.x * Ss;
    const long ob = (long)blockIdx.x * Ss;
    const int tid = threadIdx.x;

    float vals[VPT];
    float mx = -INFINITY;
#pragma unroll
    for (int i = 0; i < VPT; i++) { vals[i] = p[tid + i * 256]; mx = fmaxf(mx, vals[i]); }

    __shared__ float red[256];
    red[tid] = mx; __syncthreads();
    for (int s = 128; s > 0; s >>= 1) { if (tid < s) red[tid] = fmaxf(red[tid], red[tid + s]); __syncthreads(); }
    mx = red[0]; __syncthreads();

    float sum = 0.f;
#pragma unroll
    for (int i = 0; i < VPT; i++) { vals[i] = __expf(vals[i] - mx); sum += vals[i]; }
    red[tid] = sum; __syncthreads();
    for (int s = 128; s > 0; s >>= 1) { if (tid < s) red[tid] += red[tid + s]; __syncthreads(); }
    const float inv = 1.f / red[0];

#pragma unroll
    for (int i = 0; i < VPT; i++)
        Ph[ob + tid + i * 256] = __float2half(vals[i] * inv);
}

// ===========================================================================
extern "C" void kernel_launch(void* const* d_in, const int* in_sizes, int n_in,
                              void* d_out, int out_size)
{
    const float* x  = (const float*)d_in[0];
    const float* Wq = (const float*)d_in[1];
    const float* bq = (const float*)d_in[2];
    const float* Wk = (const float*)d_in[3];
    const float* bk = (const float*)d_in[4];
    const float* Wv = (const float*)d_in[5];
    const float* bv = (const float*)d_in[6];
    const float* Wo = (const float*)d_in[7];
    const float* bo = (const float*)d_in[8];
    float* out = (float*)d_out;

    __half *xh, *Wqh, *Wql, *Wkh, *Wkl, *Wvh, *Wvl, *Woh, *Wol;
    __half *Qh, *Kh, *Kl, *Vth, *Vtl, *Ph, *Oh;
    float* P;
    cudaGetSymbolAddress((void**)&xh, g_xh);
    cudaGetSymbolAddress((void**)&Wqh, g_Wqh); cudaGetSymbolAddress((void**)&Wql, g_Wql);
    cudaGetSymbolAddress((void**)&Wkh, g_Wkh); cudaGetSymbolAddress((void**)&Wkl, g_Wkl);
    cudaGetSymbolAddress((void**)&Wvh, g_Wvh); cudaGetSymbolAddress((void**)&Wvl, g_Wvl);
    cudaGetSymbolAddress((void**)&Woh, g_Woh); cudaGetSymbolAddress((void**)&Wol, g_Wol);
    cudaGetSymbolAddress((void**)&Qh, g_Qh);
    cudaGetSymbolAddress((void**)&Kh, g_Kh);   cudaGetSymbolAddress((void**)&Kl, g_Kl);
    cudaGetSymbolAddress((void**)&Vth, g_Vth); cudaGetSymbolAddress((void**)&Vtl, g_Vtl);
    cudaGetSymbolAddress((void**)&P, g_P);
    cudaGetSymbolAddress((void**)&Ph, g_Ph);
    cudaGetSymbolAddress((void**)&Oh, g_Oh);

    cudaFuncSetAttribute(hgemm<1, true, false>,  cudaFuncAttributeMaxDynamicSharedMemorySize, SMEM_TOTAL);
    cudaFuncSetAttribute(hgemm<2, true, false>,  cudaFuncAttributeMaxDynamicSharedMemorySize, SMEM_TOTAL);
    cudaFuncSetAttribute(hgemm<3, true, false>,  cudaFuncAttributeMaxDynamicSharedMemorySize, SMEM_TOTAL);
    cudaFuncSetAttribute(hgemm<0, false, true>,  cudaFuncAttributeMaxDynamicSharedMemorySize, SMEM_TOTAL);
    cudaFuncSetAttribute(hgemm<1, false, false>, cudaFuncAttributeMaxDynamicSharedMemorySize, SMEM_TOTAL);
    cudaFuncSetAttribute(hgemm<0, true, false>,  cudaFuncAttributeMaxDynamicSharedMemorySize, SMEM_TOTAL);

    // 1) conversions: x (hi only), W's (hi+lo)
    conv_h<<<(MQ * Dd / 4 + 255) / 256, 256>>>(x, xh, (long)MQ * Dd / 4);
    {
        dim3 gw((Dd * Dd / 4 + 255) / 256, 4, 1);
        split_w4<<<gw, 256>>>(Wq, Wqh, Wql, Wk, Wkh, Wkl,
                              Wv, Wvh, Wvl, Wo, Woh, Wol, (long)Dd * Dd / 4);
    }

    // 2) projections (CTA tile 256x128)
    dim3 gproj(Dd / 128, MQ / 256, 1);
    hgemm<1, true, false><<<gproj, 512, SMEM_TOTAL>>>(
        xh, Wqh, Wql, bq, nullptr, Qh, nullptr, MQ, Dd, Dd, 0, 0, 0, 1.f);
    hgemm<2, true, false><<<gproj, 512, SMEM_TOTAL>>>(
        xh, Wkh, Wkl, bk, nullptr, Kh, Kl, MQ, Dd, Dd, 0, 0, 0, 1.f);
    hgemm<3, true, false><<<gproj, 512, SMEM_TOTAL>>>(
        xh, Wvh, Wvl, bv, nullptr, Vth, Vtl, MQ, Dd, Dd, 0, 0, 0, 1.f);

    // 3) scores = (Q @ K^T)/32 * mask(key) -> fp32 P, batched  [ncu captures this]
    dim3 gsc(Ss / 128, Ss / 256, Bb);
    hgemm<0, false, true><<<gsc, 512, SMEM_TOTAL>>>(
        Qh, Kh, Kl, nullptr, P, nullptr, nullptr,
        Ss, Ss, Dd, (long)Ss * Dd, (long)Ss * Dd, (long)Ss * Ss, 1.f / 32.f);

    // 4) softmax -> P hi
    softmax_h<<<Bb * Ss, 256>>>(P, Ph);

    // 5) O = P @ Vt^T
    dim3 gpv(Dd / 128, Ss / 256, Bb);
    hgemm<1, false, false><<<gpv, 512, SMEM_TOTAL>>>(
        Ph, Vth, Vtl, nullptr, nullptr, Oh, nullptr,
        Ss, Dd, Ss, (long)Ss * Ss, (long)Dd * Ss, (long)Ss * Dd, 1.f);

    // 6) out = O @ Wo^T + bo -> fp32
    hgemm<0, true, false><<<gproj, 512, SMEM_TOTAL>>>(
        Oh, Woh, Wol, bo, out, nullptr, nullptr, MQ, Dd, Dd, 0, 0, 0, 1.f);
}

// round 14
// speedup vs baseline: 3.8429x; 1.7302x over previous
#include <cuda_runtime.h>
#include <cuda_fp16.h>
#include <math.h>
#include <stdint.h>

// ===========================================================================
// Problem constants
// ===========================================================================
constexpr int Bb = 4;
constexpr int Ss = 2048;
constexpr int Dd = 1024;
constexpr int MQ = Bb * Ss;                 // 8192

// ===========================================================================
// Scratch (device globals; no allocation allowed). Pure fp16 (1-pass) now.
// ===========================================================================
__device__ __half g_xh [(size_t)MQ * Dd];
__device__ __half g_Wqh[(size_t)Dd * Dd], g_Wkh[(size_t)Dd * Dd];
__device__ __half g_Wvh[(size_t)Dd * Dd], g_Woh[(size_t)Dd * Dd];
__device__ __half g_Qh [(size_t)MQ * Dd];
__device__ __half g_Kh [(size_t)MQ * Dd];
__device__ __half g_Vth[(size_t)MQ * Dd];                       // [b][d][s]
__device__ float  g_P  [(size_t)Bb * Ss * Ss];
__device__ __half g_Ph [(size_t)Bb * Ss * Ss];
__device__ __half g_Oh [(size_t)MQ * Dd];

// ===========================================================================
// Helpers (baseline sm_80+ instructions only; compute_103 has no tcgen05/TMA)
// ===========================================================================
__device__ __forceinline__ uint32_t smem_to_u32(const void* p) {
    uint32_t a;
    asm("{ .reg .u64 t; cvta.to.shared.u64 t, %1; cvt.u32.u64 %0, t; }" : "=r"(a) : "l"(p));
    return a;
}
__device__ __forceinline__ uint32_t swz(uint32_t b) { return b ^ ((b >> 3) & 0x70); }

#define CP_ASYNC16(smem_u32, gptr) \
    asm volatile("cp.async.cg.shared.global [%0], [%1], 16;" :: "r"(smem_u32), "l"(gptr) : "memory")
#define CP_COMMIT() asm volatile("cp.async.commit_group;" ::: "memory")
#define CP_WAIT1()  asm volatile("cp.async.wait_group 1;" ::: "memory")

#define LDSM_X4(r, addr) \
    asm volatile("ldmatrix.sync.aligned.m8n8.x4.shared.b16 {%0,%1,%2,%3}, [%4];" \
        : "=r"((r)[0]), "=r"((r)[1]), "=r"((r)[2]), "=r"((r)[3]) : "r"(addr))

#define MMA16816(d, a, b) \
    asm volatile("mma.sync.aligned.m16n8k16.row.col.f32.f16.f16.f32 " \
        "{%0,%1,%2,%3}, {%4,%5,%6,%7}, {%8,%9}, {%0,%1,%2,%3};" \
        : "+f"((d)[0]), "+f"((d)[1]), "+f"((d)[2]), "+f"((d)[3]) \
        : "r"((a)[0]), "r"((a)[1]), "r"((a)[2]), "r"((a)[3]), \
          "r"((b)[0]), "r"((b)[1]))

// ===========================================================================
// Plain fp16 GEMM:  C = (A @ B^T) * scale (+bias) (*gaussian mask)
// CTA tile 256x128, BK=64; 256 threads = 8 warps (4x2), warp tile 64x64.
// OUT_MODE: 0=fp32 C; 1=f16 C; 2=f16 C, V-transposed
// ===========================================================================
constexpr int STAGES = 3;
constexpr int TILE_A = 256 * 128;                  // 32 KB (256 rows x 64 f16)
constexpr int TILE_B = 128 * 128;                  // 16 KB
constexpr int STAGE_BYTES = TILE_A + TILE_B;       // 48 KB
constexpr int SMEM_TOTAL = STAGES * STAGE_BYTES + 1024;   // ~145 KB

template <int OUT_MODE, bool HAS_BIAS, bool MASK>
__global__ __launch_bounds__(256, 1)
void hgemm(const __half* __restrict__ Ah, const __half* __restrict__ Bh,
           const float* __restrict__ bias,
           float* __restrict__ Cf, __half* __restrict__ Ch,
           int M, int N, int K, long sA, long sB, long sC, float scale)
{
    extern __shared__ char smem[];
    char* smem_al = (char*)(((uintptr_t)smem + 1023ull) & ~1023ull);
    const uint32_t smem_base = smem_to_u32(smem_al);

    const int tid = threadIdx.x, wid = tid >> 5, lane = tid & 31;
    const int m0 = blockIdx.y * 256, n0 = blockIdx.x * 128;
    const int z = blockIdx.z;
    const int wm = wid >> 1, wn = wid & 1;        // warp tile: 64x64

    Ah += (long)z * sA;
    Bh += (long)z * sB;

    // --- cp.async geometry: A = 2048 16B chunks (8/thread); B = 1024 (4/thread)
    const int r0    = tid >> 3;                   // base row 0..31
    const int colel = (tid & 7) * 8;              // f16 col within 64-col chunk
    uint32_t so[8];
#pragma unroll
    for (int i = 0; i < 8; i++) so[i] = swz((uint32_t)(r0 + 32 * i) * 128 + (tid & 7) * 16);

    const int nC = K >> 6;

    auto load_chunk = [&](int chunk, int buf) {
        const uint32_t sb = smem_base + buf * STAGE_BYTES;
        const long koff = (long)chunk * 64 + colel;
        {   // A: 256 rows
            const __half* base = Ah + (long)m0 * K + koff;
#pragma unroll
            for (int i = 0; i < 8; i++)
                CP_ASYNC16(sb + so[i], base + (long)(r0 + 32 * i) * K);
        }
        {   // B: 128 rows
            const __half* base = Bh + (long)n0 * K + koff;
            const uint32_t stb = sb + TILE_A;
#pragma unroll
            for (int i = 0; i < 4; i++)
                CP_ASYNC16(stb + so[i], base + (long)(r0 + 32 * i) * K);
        }
    };

    // --- ldmatrix lane geometry
    const int arow = (lane & 7) + ((lane >> 3) & 1) * 8;
    const uint32_t acol = ((lane >> 4) & 1) * 16;
    const int brow = (lane & 7) + ((lane >> 4) & 1) * 8;
    const uint32_t bcol = ((lane >> 3) & 1) * 16;
    uint32_t rA[4], rB[4];
#pragma unroll
    for (int mi = 0; mi < 4; mi++) rA[mi] = (uint32_t)(wm * 64 + mi * 16 + arow) * 128;
#pragma unroll
    for (int n2 = 0; n2 < 4; n2++) rB[n2] = (uint32_t)(wn * 64 + n2 * 16 + brow) * 128;

    float acc[4][8][4];
#pragma unroll
    for (int mi = 0; mi < 4; mi++)
#pragma unroll
        for (int ni = 0; ni < 8; ni++)
#pragma unroll
            for (int f = 0; f < 4; f++) acc[mi][ni][f] = 0.f;

    auto compute = [&](int buf) {
        const uint32_t sbA = smem_base + buf * STAGE_BYTES;
        const uint32_t sbB = sbA + TILE_A;
#pragma unroll
        for (int ks = 0; ks < 4; ks++) {
            uint32_t ah[4][4], bh[4][4];
#pragma unroll
            for (int mi = 0; mi < 4; mi++)
                LDSM_X4(ah[mi], sbA + swz(rA[mi] + ks * 32 + acol));
#pragma unroll
            for (int n2 = 0; n2 < 4; n2++)
                LDSM_X4(bh[n2], sbB + swz(rB[n2] + ks * 32 + bcol));
#pragma unroll
            for (int mi = 0; mi < 4; mi++)
#pragma unroll
                for (int ni = 0; ni < 8; ni++)
                    MMA16816(acc[mi][ni], ah[mi], (&bh[ni >> 1][(ni & 1) * 2]));
        }
    };

    // --- pipeline
    load_chunk(0, 0); CP_COMMIT();
    load_chunk(1, 1); CP_COMMIT();

    for (int i = 0; i < nC; i++) {
        CP_WAIT1();
        __syncthreads();
        if (i + 2 < nC) load_chunk(i + 2, (i + 2) % STAGES);
        CP_COMMIT();
        compute(i % STAGES);
    }

    // --- epilogue ----------------------------------------------------------
    constexpr int TP = 264;   // padded row (elements) for the transpose tile (256+8)
    __half* Thi = (__half*)smem_al;

    if (OUT_MODE == 2) __syncthreads();   // stage buffers repurposed

#pragma unroll
    for (int mi = 0; mi < 4; mi++) {
#pragma unroll
        for (int ni = 0; ni < 8; ni++) {
            const float* c = acc[mi][ni];
            const int mA = m0 + wm * 64 + mi * 16 + (lane >> 2);
            const int nA = n0 + wn * 64 + ni * 8 + (lane & 3) * 2;
#pragma unroll
            for (int h = 0; h < 2; h++) {
                const int m = mA + h * 8;
                float v0 = c[2 * h + 0] * scale;
                float v1 = c[2 * h + 1] * scale;
                if (HAS_BIAS) { v0 += bias[nA]; v1 += bias[nA + 1]; }
                if (MASK) {
                    float u0 = ((float)nA       - 0.5f * (float)N) / (0.25f * (float)N);
                    float u1 = ((float)(nA + 1) - 0.5f * (float)N) / (0.25f * (float)N);
                    v0 *= __expf(-0.5f * u0 * u0);
                    v1 *= __expf(-0.5f * u1 * u1);
                }
                if (OUT_MODE == 0) {
                    *(float2*)(Cf + (long)z * sC + (long)m * N + nA) = make_float2(v0, v1);
                } else if (OUT_MODE == 1) {
                    const long cb = (long)z * sC + (long)m * N + nA;
                    *(__half2*)(Ch + cb) = __halves2half2(__float2half(v0), __float2half(v1));
                } else {
                    // stage transposed into smem: T[n_local][m_local]
                    const int ml = m - m0;
                    const int nl0 = nA - n0;
                    Thi[nl0 * TP + ml]       = __float2half(v0);
                    Thi[(nl0 + 1) * TP + ml] = __float2half(v1);
                }
            }
        }
    }

    if (OUT_MODE == 2) {
        __syncthreads();
        // coalesced store: Vt[b][n][s]; CTA covers n in [n0,n0+128), s in [m0,m0+256)
        const int r = tid >> 1;               // 0..127 (local n)
        const int hf = tid & 1;               // 0/1 -> 128-element halves of 256
        const long gb = ((long)(m0 >> 11) << 21) + ((long)(n0 + r) << 11)
                      + (long)(m0 & 2047) + hf * 128;
        const uint4* sh = (const uint4*)(Thi + r * TP + hf * 128);
        uint4* dh = (uint4*)(Ch + gb);
#pragma unroll
        for (int q = 0; q < 16; q++) dh[q] = sh[q];
    }
}

// ===========================================================================
// fp32 -> f16 conversions
// ===========================================================================
__global__ __launch_bounds__(256)
void conv_h(const float* __restrict__ s, __half* __restrict__ hi, long n4)
{
    long i = (long)blockIdx.x * blockDim.x + threadIdx.x;
    if (i >= n4) return;
    float4 v = *(const float4*)(s + i * 4);
    *(__half2*)(hi + i * 4)     = __halves2half2(__float2half(v.x), __float2half(v.y));
    *(__half2*)(hi + i * 4 + 2) = __halves2half2(__float2half(v.z), __float2half(v.w));
}

// All four weight matrices in one launch (blockIdx.y selects the tensor)
__global__ __launch_bounds__(256)
void conv_w4(const float* __restrict__ w0, __half* __restrict__ h0,
             const float* __restrict__ w1, __half* __restrict__ h1,
             const float* __restrict__ w2, __half* __restrict__ h2,
             const float* __restrict__ w3, __half* __restrict__ h3,
             long n4)
{
    long i = (long)blockIdx.x * blockDim.x + threadIdx.x;
    if (i >= n4) return;
    const float* s;
    __half* hi;
    switch (blockIdx.y) {
        case 0: s = w0; hi = h0; break;
        case 1: s = w1; hi = h1; break;
        case 2: s = w2; hi = h2; break;
        default: s = w3; hi = h3; break;
    }
    float4 v = *(const float4*)(s + i * 4);
    *(__half2*)(hi + i * 4)     = __halves2half2(__float2half(v.x), __float2half(v.y));
    *(__half2*)(hi + i * 4 + 2) = __halves2half2(__float2half(v.z), __float2half(v.w));
}

// ===========================================================================
// Row softmax (len 2048) fp32 in -> f16 out
// ===========================================================================
__global__ __launch_bounds__(256)
void softmax_h(const float* __restrict__ P, __half* __restrict__ Ph)
{
    constexpr int VPT = Ss / 256;
    const float* p = P + (long)blockIdx.x * Ss;
    const long ob = (long)blockIdx.x * Ss;
    const int tid = threadIdx.x;

    float vals[VPT];
    float mx = -INFINITY;
#pragma unroll
    for (int i = 0; i < VPT; i++) { vals[i] = p[tid + i * 256]; mx = fmaxf(mx, vals[i]); }

    __shared__ float red[256];
    red[tid] = mx; __syncthreads();
    for (int s = 128; s > 0; s >>= 1) { if (tid < s) red[tid] = fmaxf(red[tid], red[tid + s]); __syncthreads(); }
    mx = red[0]; __syncthreads();

    float sum = 0.f;
#pragma unroll
    for (int i = 0; i < VPT; i++) { vals[i] = __expf(vals[i] - mx); sum += vals[i]; }
    red[tid] = sum; __syncthreads();
    for (int s = 128; s > 0; s >>= 1) { if (tid < s) red[tid] += red[tid + s]; __syncthreads(); }
    const float inv = 1.f / red[0];

#pragma unroll
    for (int i = 0; i < VPT; i++)
        Ph[ob + tid + i * 256] = __float2half(vals[i] * inv);
}

// ===========================================================================
extern "C" void kernel_launch(void* const* d_in, const int* in_sizes, int n_in,
                              void* d_out, int out_size)
{
    const float* x  = (const float*)d_in[0];
    const float* Wq = (const float*)d_in[1];
    const float* bq = (const float*)d_in[2];
    const float* Wk = (const float*)d_in[3];
    const float* bk = (const float*)d_in[4];
    const float* Wv = (const float*)d_in[5];
    const float* bv = (const float*)d_in[6];
    const float* Wo = (const float*)d_in[7];
    const float* bo = (const float*)d_in[8];
    float* out = (float*)d_out;

    __half *xh, *Wqh, *Wkh, *Wvh, *Woh, *Qh, *Kh, *Vth, *Ph, *Oh;
    float* P;
    cudaGetSymbolAddress((void**)&xh, g_xh);
    cudaGetSymbolAddress((void**)&Wqh, g_Wqh);
    cudaGetSymbolAddress((void**)&Wkh, g_Wkh);
    cudaGetSymbolAddress((void**)&Wvh, g_Wvh);
    cudaGetSymbolAddress((void**)&Woh, g_Woh);
    cudaGetSymbolAddress((void**)&Qh, g_Qh);
    cudaGetSymbolAddress((void**)&Kh, g_Kh);
    cudaGetSymbolAddress((void**)&Vth, g_Vth);
    cudaGetSymbolAddress((void**)&P, g_P);
    cudaGetSymbolAddress((void**)&Ph, g_Ph);
    cudaGetSymbolAddress((void**)&Oh, g_Oh);

    cudaFuncSetAttribute(hgemm<1, true, false>,  cudaFuncAttributeMaxDynamicSharedMemorySize, SMEM_TOTAL);
    cudaFuncSetAttribute(hgemm<2, true, false>,  cudaFuncAttributeMaxDynamicSharedMemorySize, SMEM_TOTAL);
    cudaFuncSetAttribute(hgemm<0, false, true>,  cudaFuncAttributeMaxDynamicSharedMemorySize, SMEM_TOTAL);
    cudaFuncSetAttribute(hgemm<1, false, false>, cudaFuncAttributeMaxDynamicSharedMemorySize, SMEM_TOTAL);
    cudaFuncSetAttribute(hgemm<0, true, false>,  cudaFuncAttributeMaxDynamicSharedMemorySize, SMEM_TOTAL);

    // 1) conversions: x, W's (all f16 hi only)
    conv_h<<<(MQ * Dd / 4 + 255) / 256, 256>>>(x, xh, (long)MQ * Dd / 4);
    {
        dim3 gw((Dd * Dd / 4 + 255) / 256, 4, 1);
        conv_w4<<<gw, 256>>>(Wq, Wqh, Wk, Wkh, Wv, Wvh, Wo, Woh, (long)Dd * Dd / 4);
    }

    // 2) projections (CTA tile 256x128)
    dim3 gproj(Dd / 128, MQ / 256, 1);
    hgemm<1, true, false><<<gproj, 256, SMEM_TOTAL>>>(
        xh, Wqh, bq, nullptr, Qh, MQ, Dd, Dd, 0, 0, 0, 1.f);
    hgemm<1, true, false><<<gproj, 256, SMEM_TOTAL>>>(
        xh, Wkh, bk, nullptr, Kh, MQ, Dd, Dd, 0, 0, 0, 1.f);
    hgemm<2, true, false><<<gproj, 256, SMEM_TOTAL>>>(
        xh, Wvh, bv, nullptr, Vth, MQ, Dd, Dd, 0, 0, 0, 1.f);

    // 3) scores = (Q @ K^T)/32 * mask(key) -> fp32 P, batched  [ncu captures this]
    dim3 gsc(Ss / 128, Ss / 256, Bb);
    hgemm<0, false, true><<<gsc, 256, SMEM_TOTAL>>>(
        Qh, Kh, nullptr, P, nullptr,
        Ss, Ss, Dd, (long)Ss * Dd, (long)Ss * Dd, (long)Ss * Ss, 1.f / 32.f);

    // 4) softmax -> P f16
    softmax_h<<<Bb * Ss, 256>>>(P, Ph);

    // 5) O = P @ Vt^T
    dim3 gpv(Dd / 128, Ss / 256, Bb);
    hgemm<1, false, false><<<gpv, 256, SMEM_TOTAL>>>(
        Ph, Vth, nullptr, nullptr, Oh,
        Ss, Dd, Ss, (long)Ss * Ss, (long)Dd * Ss, (long)Ss * Dd, 1.f);

    // 6) out = O @ Wo^T + bo -> fp32
    hgemm<0, true, false><<<gproj, 256, SMEM_TOTAL>>>(
        Oh, Woh, bo, out, nullptr, MQ, Dd, Dd, 0, 0, 0, 1.f);
}

// round 16
// speedup vs baseline: 3.8905x; 1.0124x over previous
#include <cuda_runtime.h>
#include <cuda_fp16.h>
#include <math.h>
#include <stdint.h>

// ===========================================================================
// Problem constants
// ===========================================================================
constexpr int Bb = 4;
constexpr int Ss = 2048;
constexpr int Dd = 1024;
constexpr int MQ = Bb * Ss;                 // 8192

// ===========================================================================
// Scratch (device globals; no allocation allowed). Pure fp16 (1-pass).
// ===========================================================================
__device__ __half g_xh [(size_t)MQ * Dd];
__device__ __half g_Wqh[(size_t)Dd * Dd], g_Wkh[(size_t)Dd * Dd];
__device__ __half g_Wvh[(size_t)Dd * Dd], g_Woh[(size_t)Dd * Dd];
__device__ __half g_Qh [(size_t)MQ * Dd];
__device__ __half g_Kh [(size_t)MQ * Dd];
__device__ __half g_Vth[(size_t)MQ * Dd];                       // [b][d][s]
__device__ float  g_P  [(size_t)Bb * Ss * Ss];
__device__ __half g_Ph [(size_t)Bb * Ss * Ss];
__device__ __half g_Oh [(size_t)MQ * Dd];

// ===========================================================================
// Helpers (baseline sm_80+ instructions only; compute_103 has no tcgen05/TMA)
// ===========================================================================
__device__ __forceinline__ uint32_t smem_to_u32(const void* p) {
    uint32_t a;
    asm("{ .reg .u64 t; cvta.to.shared.u64 t, %1; cvt.u32.u64 %0, t; }" : "=r"(a) : "l"(p));
    return a;
}
__device__ __forceinline__ uint32_t swz(uint32_t b) { return b ^ ((b >> 3) & 0x70); }

#define CP_ASYNC16(smem_u32, gptr) \
    asm volatile("cp.async.cg.shared.global [%0], [%1], 16;" :: "r"(smem_u32), "l"(gptr) : "memory")
#define CP_COMMIT() asm volatile("cp.async.commit_group;" ::: "memory")
#define CP_WAIT1()  asm volatile("cp.async.wait_group 1;" ::: "memory")

#define LDSM_X4(r, addr) \
    asm volatile("ldmatrix.sync.aligned.m8n8.x4.shared.b16 {%0,%1,%2,%3}, [%4];" \
        : "=r"((r)[0]), "=r"((r)[1]), "=r"((r)[2]), "=r"((r)[3]) : "r"(addr))

#define MMA16816(d, a, b) \
    asm volatile("mma.sync.aligned.m16n8k16.row.col.f32.f16.f16.f32 " \
        "{%0,%1,%2,%3}, {%4,%5,%6,%7}, {%8,%9}, {%0,%1,%2,%3};" \
        : "+f"((d)[0]), "+f"((d)[1]), "+f"((d)[2]), "+f"((d)[3]) \
        : "r"((a)[0]), "r"((a)[1]), "r"((a)[2]), "r"((a)[3]), \
          "r"((b)[0]), "r"((b)[1]))

// ===========================================================================
// Plain fp16 GEMM:  C = (A @ B^T) * scale (+bias) (*gaussian mask)
// CTA tile 128x128, BK=64; 256 threads = 8 warps (2x4), warp tile 64x32.
// __launch_bounds__(256, 2): 2 CTAs/SM (regs<=128) so independent CTAs
// cover each other's pipeline bubbles -> tensor pipe stays fed.
// OUT_MODE: 0=fp32 C; 1=f16 C; 2=f16 C, V-transposed
// ===========================================================================
constexpr int STAGES = 3;
constexpr int TILE_A = 128 * 128;                  // 16 KB (128 rows x 64 f16)
constexpr int TILE_B = 128 * 128;                  // 16 KB
constexpr int STAGE_BYTES = TILE_A + TILE_B;       // 32 KB
constexpr int SMEM_TOTAL = STAGES * STAGE_BYTES + 1024;   // ~97 KB (2 CTAs fit)

template <int OUT_MODE, bool HAS_BIAS, bool MASK>
__global__ __launch_bounds__(256, 2)
void hgemm(const __half* __restrict__ Ah, const __half* __restrict__ Bh,
           const float* __restrict__ bias,
           float* __restrict__ Cf, __half* __restrict__ Ch,
           int M, int N, int K, long sA, long sB, long sC, float scale)
{
    extern __shared__ char smem[];
    char* smem_al = (char*)(((uintptr_t)smem + 1023ull) & ~1023ull);
    const uint32_t smem_base = smem_to_u32(smem_al);

    const int tid = threadIdx.x, wid = tid >> 5, lane = tid & 31;
    const int m0 = blockIdx.y * 128, n0 = blockIdx.x * 128;
    const int z = blockIdx.z;
    const int wm = wid >> 2, wn = wid & 3;        // 2x4 warps, warp tile 64x32

    Ah += (long)z * sA;
    Bh += (long)z * sB;

    // --- cp.async geometry: each 16KB tile = 1024 x 16B chunks; 4/thread
    const int r0    = tid >> 3;                   // base row 0..31
    const int colel = (tid & 7) * 8;              // f16 col within 64-col chunk
    uint32_t so[4];
#pragma unroll
    for (int i = 0; i < 4; i++) so[i] = swz((uint32_t)(r0 + 32 * i) * 128 + (tid & 7) * 16);

    const int nC = K >> 6;

    auto load_chunk = [&](int chunk, int buf) {
        const uint32_t sb = smem_base + buf * STAGE_BYTES;
        const long koff = (long)chunk * 64 + colel;
        {   // A: 128 rows
            const __half* base = Ah + (long)m0 * K + koff;
#pragma unroll
            for (int i = 0; i < 4; i++)
                CP_ASYNC16(sb + so[i], base + (long)(r0 + 32 * i) * K);
        }
        {   // B: 128 rows
            const __half* base = Bh + (long)n0 * K + koff;
            const uint32_t stb = sb + TILE_A;
#pragma unroll
            for (int i = 0; i < 4; i++)
                CP_ASYNC16(stb + so[i], base + (long)(r0 + 32 * i) * K);
        }
    };

    // --- ldmatrix lane geometry
    const int arow = (lane & 7) + ((lane >> 3) & 1) * 8;
    const uint32_t acol = ((lane >> 4) & 1) * 16;
    const int brow = (lane & 7) + ((lane >> 4) & 1) * 8;
    const uint32_t bcol = ((lane >> 3) & 1) * 16;
    uint32_t rA[4], rB[2];
#pragma unroll
    for (int mi = 0; mi < 4; mi++) rA[mi] = (uint32_t)(wm * 64 + mi * 16 + arow) * 128;
#pragma unroll
    for (int n2 = 0; n2 < 2; n2++) rB[n2] = (uint32_t)(wn * 32 + n2 * 16 + brow) * 128;

    float acc[4][4][4];
#pragma unroll
    for (int mi = 0; mi < 4; mi++)
#pragma unroll
        for (int ni = 0; ni < 4; ni++)
#pragma unroll
            for (int f = 0; f < 4; f++) acc[mi][ni][f] = 0.f;

    auto compute = [&](int buf) {
        const uint32_t sbA = smem_base + buf * STAGE_BYTES;
        const uint32_t sbB = sbA + TILE_A;
#pragma unroll
        for (int ks = 0; ks < 4; ks++) {
            uint32_t ah[4][4], bh[2][4];
#pragma unroll
            for (int mi = 0; mi < 4; mi++)
                LDSM_X4(ah[mi], sbA + swz(rA[mi] + ks * 32 + acol));
#pragma unroll
            for (int n2 = 0; n2 < 2; n2++)
                LDSM_X4(bh[n2], sbB + swz(rB[n2] + ks * 32 + bcol));
#pragma unroll
            for (int mi = 0; mi < 4; mi++)
#pragma unroll
                for (int ni = 0; ni < 4; ni++)
                    MMA16816(acc[mi][ni], ah[mi], (&bh[ni >> 1][(ni & 1) * 2]));
        }
    };

    // --- pipeline
    load_chunk(0, 0); CP_COMMIT();
    load_chunk(1, 1); CP_COMMIT();

    for (int i = 0; i < nC; i++) {
        CP_WAIT1();
        __syncthreads();
        if (i + 2 < nC) load_chunk(i + 2, (i + 2) % STAGES);
        CP_COMMIT();
        compute(i % STAGES);
    }

    // --- epilogue ----------------------------------------------------------
    constexpr int TP = 136;   // padded row (elements) for the transpose tile (128+8)
    __half* Thi = (__half*)smem_al;

    if (OUT_MODE == 2) __syncthreads();   // stage buffers repurposed

#pragma unroll
    for (int mi = 0; mi < 4; mi++) {
#pragma unroll
        for (int ni = 0; ni < 4; ni++) {
            const float* c = acc[mi][ni];
            const int mA = m0 + wm * 64 + mi * 16 + (lane >> 2);
            const int nA = n0 + wn * 32 + ni * 8 + (lane & 3) * 2;
#pragma unroll
            for (int h = 0; h < 2; h++) {
                const int m = mA + h * 8;
                float v0 = c[2 * h + 0] * scale;
                float v1 = c[2 * h + 1] * scale;
                if (HAS_BIAS) { v0 += bias[nA]; v1 += bias[nA + 1]; }
                if (MASK) {
                    float u0 = ((float)nA       - 0.5f * (float)N) / (0.25f * (float)N);
                    float u1 = ((float)(nA + 1) - 0.5f * (float)N) / (0.25f * (float)N);
                    v0 *= __expf(-0.5f * u0 * u0);
                    v1 *= __expf(-0.5f * u1 * u1);
                }
                if (OUT_MODE == 0) {
                    *(float2*)(Cf + (long)z * sC + (long)m * N + nA) = make_float2(v0, v1);
                } else if (OUT_MODE == 1) {
                    const long cb = (long)z * sC + (long)m * N + nA;
                    *(__half2*)(Ch + cb) = __halves2half2(__float2half(v0), __float2half(v1));
                } else {
                    // stage transposed into smem: T[n_local][m_local]
                    const int ml = m - m0;
                    const int nl0 = nA - n0;
                    Thi[nl0 * TP + ml]       = __float2half(v0);
                    Thi[(nl0 + 1) * TP + ml] = __float2half(v1);
                }
            }
        }
    }

    if (OUT_MODE == 2) {
        __syncthreads();
        // coalesced store: Vt[b][n][s]; CTA covers n in [n0,n0+128), s in [m0,m0+128)
        const int r = tid >> 1;               // 0..127 (local n)
        const int hf = tid & 1;               // 0/1 -> 64-element halves of 128
        const long gb = ((long)(m0 >> 11) << 21) + ((long)(n0 + r) << 11)
                      + (long)(m0 & 2047) + hf * 64;
        const uint4* sh = (const uint4*)(Thi + r * TP + hf * 64);
        uint4* dh = (uint4*)(Ch + gb);
#pragma unroll
        for (int q = 0; q < 8; q++) dh[q] = sh[q];
    }
}

// ===========================================================================
// fp32 -> f16 conversions
// ===========================================================================
__global__ __launch_bounds__(256)
void conv_h(const float* __restrict__ s, __half* __restrict__ hi, long n4)
{
    long i = (long)blockIdx.x * blockDim.x + threadIdx.x;
    if (i >= n4) return;
    float4 v = *(const float4*)(s + i * 4);
    *(__half2*)(hi + i * 4)     = __halves2half2(__float2half(v.x), __float2half(v.y));
    *(__half2*)(hi + i * 4 + 2) = __halves2half2(__float2half(v.z), __float2half(v.w));
}

// All four weight matrices in one launch (blockIdx.y selects the tensor)
__global__ __launch_bounds__(256)
void conv_w4(const float* __restrict__ w0, __half* __restrict__ h0,
             const float* __restrict__ w1, __half* __restrict__ h1,
             const float* __restrict__ w2, __half* __restrict__ h2,
             const float* __restrict__ w3, __half* __restrict__ h3,
             long n4)
{
    long i = (long)blockIdx.x * blockDim.x + threadIdx.x;
    if (i >= n4) return;
    const float* s;
    __half* hi;
    switch (blockIdx.y) {
        case 0: s = w0; hi = h0; break;
        case 1: s = w1; hi = h1; break;
        case 2: s = w2; hi = h2; break;
        default: s = w3; hi = h3; break;
    }
    float4 v = *(const float4*)(s + i * 4);
    *(__half2*)(hi + i * 4)     = __halves2half2(__float2half(v.x), __float2half(v.y));
    *(__half2*)(hi + i * 4 + 2) = __halves2half2(__float2half(v.z), __float2half(v.w));
}

// ===========================================================================
// Row softmax (len 2048) fp32 in -> f16 out
// ===========================================================================
__global__ __launch_bounds__(256)
void softmax_h(const float* __restrict__ P, __half* __restrict__ Ph)
{
    constexpr int VPT = Ss / 256;
    const float* p = P + (long)blockIdx.x * Ss;
    const long ob = (long)blockIdx.x * Ss;
    const int tid = threadIdx.x;

    float vals[VPT];
    float mx = -INFINITY;
#pragma unroll
    for (int i = 0; i < VPT; i++) { vals[i] = p[tid + i * 256]; mx = fmaxf(mx, vals[i]); }

    __shared__ float red[256];
    red[tid] = mx; __syncthreads();
    for (int s = 128; s > 0; s >>= 1) { if (tid < s) red[tid] = fmaxf(red[tid], red[tid + s]); __syncthreads(); }
    mx = red[0]; __syncthreads();

    float sum = 0.f;
#pragma unroll
    for (int i = 0; i < VPT; i++) { vals[i] = __expf(vals[i] - mx); sum += vals[i]; }
    red[tid] = sum; __syncthreads();
    for (int s = 128; s > 0; s >>= 1) { if (tid < s) red[tid] += red[tid + s]; __syncthreads(); }
    const float inv = 1.f / red[0];

#pragma unroll
    for (int i = 0; i < VPT; i++)
        Ph[ob + tid + i * 256] = __float2half(vals[i] * inv);
}

// ===========================================================================
extern "C" void kernel_launch(void* const* d_in, const int* in_sizes, int n_in,
                              void* d_out, int out_size)
{
    const float* x  = (const float*)d_in[0];
    const float* Wq = (const float*)d_in[1];
    const float* bq = (const float*)d_in[2];
    const float* Wk = (const float*)d_in[3];
    const float* bk = (const float*)d_in[4];
    const float* Wv = (const float*)d_in[5];
    const float* bv = (const float*)d_in[6];
    const float* Wo = (const float*)d_in[7];
    const float* bo = (const float*)d_in[8];
    float* out = (float*)d_out;

    __half *xh, *Wqh, *Wkh, *Wvh, *Woh, *Qh, *Kh, *Vth, *Ph, *Oh;
    float* P;
    cudaGetSymbolAddress((void**)&xh, g_xh);
    cudaGetSymbolAddress((void**)&Wqh, g_Wqh);
    cudaGetSymbolAddress((void**)&Wkh, g_Wkh);
    cudaGetSymbolAddress((void**)&Wvh, g_Wvh);
    cudaGetSymbolAddress((void**)&Woh, g_Woh);
    cudaGetSymbolAddress((void**)&Qh, g_Qh);
    cudaGetSymbolAddress((void**)&Kh, g_Kh);
    cudaGetSymbolAddress((void**)&Vth, g_Vth);
    cudaGetSymbolAddress((void**)&P, g_P);
    cudaGetSymbolAddress((void**)&Ph, g_Ph);
    cudaGetSymbolAddress((void**)&Oh, g_Oh);

    cudaFuncSetAttribute(hgemm<1, true, false>,  cudaFuncAttributeMaxDynamicSharedMemorySize, SMEM_TOTAL);
    cudaFuncSetAttribute(hgemm<2, true, false>,  cudaFuncAttributeMaxDynamicSharedMemorySize, SMEM_TOTAL);
    cudaFuncSetAttribute(hgemm<0, false, true>,  cudaFuncAttributeMaxDynamicSharedMemorySize, SMEM_TOTAL);
    cudaFuncSetAttribute(hgemm<1, false, false>, cudaFuncAttributeMaxDynamicSharedMemorySize, SMEM_TOTAL);
    cudaFuncSetAttribute(hgemm<0, true, false>,  cudaFuncAttributeMaxDynamicSharedMemorySize, SMEM_TOTAL);

    // 1) conversions: x, W's (all f16)
    conv_h<<<(MQ * Dd / 4 + 255) / 256, 256>>>(x, xh, (long)MQ * Dd / 4);
    {
        dim3 gw((Dd * Dd / 4 + 255) / 256, 4, 1);
        conv_w4<<<gw, 256>>>(Wq, Wqh, Wk, Wkh, Wv, Wvh, Wo, Woh, (long)Dd * Dd / 4);
    }

    // 2) projections (CTA tile 128x128, 2 CTAs/SM)
    dim3 gproj(Dd / 128, MQ / 128, 1);
    hgemm<1, true, false><<<gproj, 256, SMEM_TOTAL>>>(
        xh, Wqh, bq, nullptr, Qh, MQ, Dd, Dd, 0, 0, 0, 1.f);
    hgemm<1, true, false><<<gproj, 256, SMEM_TOTAL>>>(
        xh, Wkh, bk, nullptr, Kh, MQ, Dd, Dd, 0, 0, 0, 1.f);
    hgemm<2, true, false><<<gproj, 256, SMEM_TOTAL>>>(
        xh, Wvh, bv, nullptr, Vth, MQ, Dd, Dd, 0, 0, 0, 1.f);

    // 3) scores = (Q @ K^T)/32 * mask(key) -> fp32 P, batched  [ncu captures this]
    dim3 gsc(Ss / 128, Ss / 128, Bb);
    hgemm<0, false, true><<<gsc, 256, SMEM_TOTAL>>>(
        Qh, Kh, nullptr, P, nullptr,
        Ss, Ss, Dd, (long)Ss * Dd, (long)Ss * Dd, (long)Ss * Ss, 1.f / 32.f);

    // 4) softmax -> P f16
    softmax_h<<<Bb * Ss, 256>>>(P, Ph);

    // 5) O = P @ Vt^T
    dim3 gpv(Dd / 128, Ss / 128, Bb);
    hgemm<1, false, false><<<gpv, 256, SMEM_TOTAL>>>(
        Ph, Vth, nullptr, nullptr, Oh,
        Ss, Dd, Ss, (long)Ss * Ss, (long)Dd * Ss, (long)Ss * Dd, 1.f);

    // 6) out = O @ Wo^T + bo -> fp32
    hgemm<0, true, false><<<gproj, 256, SMEM_TOTAL>>>(
        Oh, Woh, bo, out, nullptr, MQ, Dd, Dd, 0, 0, 0, 1.f);
}